// round 11
// baseline (speedup 1.0000x reference)
#include <cuda_runtime.h>
#include <cuda_bf16.h>
#include <math.h>
#include <stdint.h>

// Problem dims (fixed)
#define B_ 64
#define D_ 512
#define M_ 1024
#define L_ 256
#define KK_ 30

typedef __nv_bfloat16 bf16;

// ===================== device scratch =========================================
__device__ bf16 g_Wv_hi[32 * D_];
__device__ bf16 g_Wv_lo[32 * D_];
__device__ bf16 g_Wq_hi[32 * D_];
__device__ bf16 g_Wq_lo[32 * D_];
__device__ bf16 g_WqQ_hi[(long)B_ * 32 * L_];
__device__ bf16 g_WqQ_lo[(long)B_ * 32 * L_];
__device__ float g_WqQ_f[(long)B_ * 32 * L_];
__device__ bf16 g_P_hi[(long)B_ * 32 * D_];
__device__ bf16 g_P_lo[(long)B_ * 32 * D_];
__device__ bf16 g_Yv_hi[(long)B_ * 32 * D_];
__device__ bf16 g_Yv_lo[(long)B_ * 32 * D_];
__device__ bf16 g_WvV_hi[(long)B_ * 32 * M_];
__device__ bf16 g_WvV_lo[(long)B_ * 32 * M_];
__device__ bf16 g_Yq_hi[(long)B_ * 32 * D_];
__device__ bf16 g_Yq_lo[(long)B_ * 32 * D_];
__device__ bf16 g_R_hi[(long)B_ * 32 * D_];
__device__ bf16 g_R_lo[(long)B_ * 32 * D_];
__device__ float g_zv[B_ * M_];
__device__ float g_zq[B_ * L_];
__device__ float g_v1[B_ * D_];
__device__ float g_q1[B_ * D_];

// scheduler state (zeroed per launch via cudaMemsetAsync)
__device__ unsigned g_cursor;
__device__ int g_cnt[7 * B_];

// ===================== helpers ================================================
__device__ __forceinline__ uint32_t s2u(const void* p) {
    return (uint32_t)__cvta_generic_to_shared(p);
}
__device__ __forceinline__ void cp16(uint32_t dst, const void* src) {
    asm volatile("cp.async.cg.shared.global [%0], [%1], 16;" :: "r"(dst), "l"(src));
}
__device__ __forceinline__ void cp_commit() { asm volatile("cp.async.commit_group;"); }
__device__ __forceinline__ void cp_wait0()  { asm volatile("cp.async.wait_group 0;"); }

__device__ __forceinline__ void ldsm4(uint32_t* r, uint32_t addr) {
    asm volatile("ldmatrix.sync.aligned.m8n8.x4.shared.b16 {%0,%1,%2,%3}, [%4];"
                 : "=r"(r[0]), "=r"(r[1]), "=r"(r[2]), "=r"(r[3]) : "r"(addr));
}
__device__ __forceinline__ void ldsm4t(uint32_t* r, uint32_t addr) {
    asm volatile("ldmatrix.sync.aligned.m8n8.x4.trans.shared.b16 {%0,%1,%2,%3}, [%4];"
                 : "=r"(r[0]), "=r"(r[1]), "=r"(r[2]), "=r"(r[3]) : "r"(addr));
}
__device__ __forceinline__ void mma_bf(float* d, const uint32_t* a, const uint32_t* b) {
    asm volatile(
        "mma.sync.aligned.m16n8k16.row.col.f32.bf16.bf16.f32 "
        "{%0,%1,%2,%3}, {%4,%5,%6,%7}, {%8,%9}, {%0,%1,%2,%3};"
        : "+f"(d[0]), "+f"(d[1]), "+f"(d[2]), "+f"(d[3])
        : "r"(a[0]), "r"(a[1]), "r"(a[2]), "r"(a[3]), "r"(b[0]), "r"(b[1]));
}
__device__ __forceinline__ void split_bf(float x, bf16& h, bf16& l) {
    h = __float2bfloat16(x);
    l = __float2bfloat16(x - __bfloat162float(h));
}

// smem layout constants (bytes) -- 64-row m-tiles, 128-thread CTAs
#define A_BUF 5120u      // AN: 64 rows x 80B ; TRA: 32 rows x 144B (4608 <= slot)
#define B_BUF 2560u      // 32 x 40 bf16
#define BS_OFF 20480u    // after 4 A slots
#define CST 132          // epilogue staging n-stride (floats)
#define SMEM_SZ (int)(BS_OFF + 2 * 4 * B_BUF + 128)   // 41088 (max: NB=2)

// ===================== weight pad conversion ==================================
__global__ void conv_pad(const float* __restrict__ Wv, bf16* __restrict__ Vh, bf16* __restrict__ Vl,
                         const float* __restrict__ Wq, bf16* __restrict__ Qh, bf16* __restrict__ Ql)
{
    int idx = blockIdx.x * blockDim.x + threadIdx.x;
    if (idx >= 32 * D_) return;
    int k = idx / D_, d = idx % D_;
    float a = (k < KK_) ? Wv[k * D_ + d] : 0.f;
    float b = (k < KK_) ? Wq[k * D_ + d] : 0.f;
    bf16 h, l;
    split_bf(a, h, l); Vh[idx] = h; Vl[idx] = l;
    split_bf(b, h, l); Qh[idx] = h; Ql[idx] = l;
}

// ===================== HMMA GEMM core (R10, params instead of blockIdx) =======
struct GJob {
    const float* A;                      // fp32 big operand
    int lda; long sA;
    const bf16 *B0h, *B0l, *B1h, *B1l;   // small operands [32][Kd] bf16
    bf16 *Ch, *Cl;                       // out [b][32][Nbig]
    float* Cf;                           // EPI1: fp32 out; EPI3: fp32 X in
    const float* w;                      // logits weights (EPI 2/3)
    float* z;                            // logits out [b][Nbig]
    int Nbig, Kd;
    long sB0, sB1;
};

// EPI: 0 = hi/lo out; 1 = hi/lo + fp32 out; 2 = (NB=2) hi/lo of acc0 + fused
//      logits(acc0+acc1); 3 = logits(acc0 + fp32 X), no C out
template<int NB, int EPI, bool TRA>
__device__ __forceinline__ void gemm_core(const GJob& j, int b, int tile)
{
    extern __shared__ char smem[];
    const uint32_t sb = s2u(smem);
    float* smw = (float*)(smem + BS_OFF + NB * 4 * B_BUF);

    const int tid = threadIdx.x;
    const int w = tid >> 5, lane = tid & 31;
    const int m0 = tile * 64;

    const float* Ab = j.A + (long)b * j.sA;
    const bf16* Bb[2][2];
    Bb[0][0] = j.B0h + (long)b * j.sB0;
    Bb[0][1] = j.B0l + (long)b * j.sB0;
    if (NB == 2) {
        Bb[1][0] = j.B1h + (long)b * j.sB1;
        Bb[1][1] = j.B1l + (long)b * j.sB1;
    }

    if (EPI >= 2 && tid < KK_) smw[tid] = j.w[tid];

    // A gmem addressing (16 floats per thread per 32-k tile)
    const float* aptr = TRA
        ? (Ab + (long)(tid >> 2) * j.lda + m0 + (tid & 3) * 16)
        : (Ab + (long)(m0 + (tid >> 1)) * j.lda + (tid & 1) * 16);
    const uint32_t aSts = TRA ? (uint32_t)((tid >> 2) * 144 + (tid & 3) * 32)
                              : (uint32_t)((tid >> 1) * 80 + (tid & 1) * 32);

    // B staging indices: 32 rows x 4 cols of 16B, both hl per thread
    const int br = tid >> 2, bc = tid & 3;

    const int T = j.Kd / 32;
    float4 fr[4];

    auto loadA = [&](int t) {
        const float* p = TRA ? (aptr + (long)t * 32 * j.lda) : (aptr + t * 32);
        fr[0] = *(const float4*)p;
        fr[1] = *(const float4*)(p + 4);
        fr[2] = *(const float4*)(p + 8);
        fr[3] = *(const float4*)(p + 12);
    };
    auto stsA = [&](int s) {
        uint32_t hp[8], lp[8];
        const float* f = (const float*)fr;
#pragma unroll
        for (int i = 0; i < 8; i++) {
            bf16 h0, l0, h1, l1;
            split_bf(f[2 * i], h0, l0);
            split_bf(f[2 * i + 1], h1, l1);
            hp[i] = (uint32_t)*(uint16_t*)&h0 | ((uint32_t)*(uint16_t*)&h1 << 16);
            lp[i] = (uint32_t)*(uint16_t*)&l0 | ((uint32_t)*(uint16_t*)&l1 << 16);
        }
        char* d0 = smem + (s * 2 + 0) * A_BUF + aSts;
        char* d1 = smem + (s * 2 + 1) * A_BUF + aSts;
        *(uint4*)d0        = make_uint4(hp[0], hp[1], hp[2], hp[3]);
        *(uint4*)(d0 + 16) = make_uint4(hp[4], hp[5], hp[6], hp[7]);
        *(uint4*)d1        = make_uint4(lp[0], lp[1], lp[2], lp[3]);
        *(uint4*)(d1 + 16) = make_uint4(lp[4], lp[5], lp[6], lp[7]);
    };
    auto stageB = [&](int t) {
        const int s = t & 1;
#pragma unroll
        for (int nb = 0; nb < NB; nb++)
#pragma unroll
        for (int hl = 0; hl < 2; hl++) {
            uint32_t dst = sb + BS_OFF + (uint32_t)(((s * NB + nb) * 2 + hl) * B_BUF)
                         + br * 80 + bc * 16;
            cp16(dst, Bb[nb][hl] + (long)br * j.Kd + t * 32 + bc * 8);
        }
        cp_commit();
    };

    // ldmatrix lane addressing
    const uint32_t aLane = TRA
        ? (uint32_t)((((lane & 7) + 8 * (lane >> 4)) * 144) + (w * 16 + ((lane >> 3) & 1) * 8) * 2)
        : (uint32_t)((w * 16 + (lane & 15)) * 80 + (lane >> 4) * 16);
    const uint32_t aKs = TRA ? 2304u : 32u;
    const uint32_t bLaneRow = (uint32_t)((((lane >> 4) & 1) * 8 + (lane & 7)) * 80
                                         + ((lane >> 3) & 1) * 16);

    float acc[NB][4][4];
#pragma unroll
    for (int nb = 0; nb < NB; nb++)
#pragma unroll
        for (int nt = 0; nt < 4; nt++)
#pragma unroll
            for (int r = 0; r < 4; r++) acc[nb][nt][r] = 0.f;

    stageB(0);
    loadA(0);

    for (int t = 0; t < T; t++) {
        const int s = t & 1;
        cp_wait0();
        __syncthreads();

        stsA(s);
        if (t + 1 < T) { stageB(t + 1); loadA(t + 1); }
        __syncthreads();

        const uint32_t aH = sb + (uint32_t)((s * 2 + 0) * A_BUF) + aLane;
        const uint32_t aL = aH + A_BUF;

#pragma unroll
        for (int ks = 0; ks < 2; ks++) {
            uint32_t ah[4], al[4];
            if (TRA) { ldsm4t(ah, aH + ks * aKs); ldsm4t(al, aL + ks * aKs); }
            else     { ldsm4 (ah, aH + ks * aKs); ldsm4 (al, aL + ks * aKs); }
#pragma unroll
            for (int nb = 0; nb < NB; nb++) {
#pragma unroll
                for (int p = 0; p < 2; p++) {
                    uint32_t bbase = sb + BS_OFF + (uint32_t)(((s * NB + nb) * 2 + 0) * B_BUF)
                        + (uint32_t)(p * 16 * 80) + bLaneRow + ks * 32;
                    uint32_t bh[4], bl[4];
                    ldsm4(bh, bbase);
                    ldsm4(bl, bbase + B_BUF);
                    mma_bf(acc[nb][2 * p],     ah, &bh[0]);
                    mma_bf(acc[nb][2 * p],     ah, &bl[0]);
                    mma_bf(acc[nb][2 * p],     al, &bh[0]);
                    mma_bf(acc[nb][2 * p + 1], ah, &bh[2]);
                    mma_bf(acc[nb][2 * p + 1], ah, &bl[2]);
                    mma_bf(acc[nb][2 * p + 1], al, &bh[2]);
                }
            }
        }
    }

    // ---------------- epilogue --------------------------------------------
    __syncthreads();
    float* Cs = (float*)smem;
    {
        const int g = lane >> 2, cc = lane & 3;
        const int m_l = w * 16 + g;
#pragma unroll
        for (int nb = 0; nb < NB; nb++) {
            float* C_ = Cs + nb * 32 * CST;
#pragma unroll
            for (int nt = 0; nt < 4; nt++) {
                int n0 = nt * 8 + cc * 2;
                C_[(n0 + 0) * CST + m_l]     = acc[nb][nt][0];
                C_[(n0 + 1) * CST + m_l]     = acc[nb][nt][1];
                C_[(n0 + 0) * CST + m_l + 8] = acc[nb][nt][2];
                C_[(n0 + 1) * CST + m_l + 8] = acc[nb][nt][3];
            }
        }
    }
    __syncthreads();

    if (EPI != 3) {
#pragma unroll
        for (int it = 0; it < 4; it++) {
            int q = tid + it * 128;
            int n = q >> 4, m4 = (q & 15) * 4;
            float4 v = *(float4*)&Cs[n * CST + m4];
            bf16 h0, l0, h1, l1, h2, l2, h3, l3;
            split_bf(v.x, h0, l0); split_bf(v.y, h1, l1);
            split_bf(v.z, h2, l2); split_bf(v.w, h3, l3);
            long o = ((long)b * 32 + n) * j.Nbig + m0 + m4;
            *(uint2*)(j.Ch + o) = make_uint2(
                ((uint32_t)*(uint16_t*)&h0) | ((uint32_t)*(uint16_t*)&h1 << 16),
                ((uint32_t)*(uint16_t*)&h2) | ((uint32_t)*(uint16_t*)&h3 << 16));
            *(uint2*)(j.Cl + o) = make_uint2(
                ((uint32_t)*(uint16_t*)&l0) | ((uint32_t)*(uint16_t*)&l1 << 16),
                ((uint32_t)*(uint16_t*)&l2) | ((uint32_t)*(uint16_t*)&l3 << 16));
            if (EPI == 1) *(float4*)(j.Cf + o) = v;
        }
    }
    if (EPI == 2) {
        if (tid < 64) {
            float zacc = 0.f;
#pragma unroll
            for (int k = 0; k < KK_; k++)
                zacc += smw[k] * tanhf(Cs[k * CST + tid] + Cs[(32 + k) * CST + tid]);
            j.z[(long)b * j.Nbig + m0 + tid] = zacc;
        }
    }
    if (EPI == 3) {
        if (tid < 64) {
            const float* X = j.Cf + (long)b * 32 * j.Nbig + m0 + tid;
            float zacc = 0.f;
#pragma unroll
            for (int k = 0; k < KK_; k++)
                zacc += smw[k] * tanhf(Cs[k * CST + tid] + X[(long)k * j.Nbig]);
            j.z[(long)b * j.Nbig + m0 + tid] = zacc;
        }
    }
}

// ===================== persistent megakernel ==================================
// Item order: (stage, b, tile). Stage ranges:
//  S0 K1 : [0,256)    4/b    S1 K2 : [256,768)  8/b   S2 K3 : [768,1280)  8/b
//  S3 K45: [1280,2304) 16/b  S4 K6 : [2304,2816) 8/b  S5 K7 : [2816,3328) 8/b
//  S6 K8 : [3328,3584) 4/b
#define N_ITEMS 3584u

struct Jobs { GJob s[7]; };

__global__ void __launch_bounds__(128, 5) mega_gemm(Jobs J)
{
    const int tid = threadIdx.x;
    __shared__ unsigned s_item;

    while (true) {
        __syncthreads();                 // protect s_item + smem reuse
        if (tid == 0) s_item = atomicAdd(&g_cursor, 1u);
        __syncthreads();
        const unsigned i = s_item;
        if (i >= N_ITEMS) break;

        int stage, b, tile;
        if      (i < 256u)  { stage = 0; unsigned r = i;         b = r >> 2; tile = r & 3;  }
        else if (i < 768u)  { stage = 1; unsigned r = i - 256u;  b = r >> 3; tile = r & 7;  }
        else if (i < 1280u) { stage = 2; unsigned r = i - 768u;  b = r >> 3; tile = r & 7;  }
        else if (i < 2304u) { stage = 3; unsigned r = i - 1280u; b = r >> 4; tile = r & 15; }
        else if (i < 2816u) { stage = 4; unsigned r = i - 2304u; b = r >> 3; tile = r & 7;  }
        else if (i < 3328u) { stage = 5; unsigned r = i - 2816u; b = r >> 3; tile = r & 7;  }
        else                { stage = 6; unsigned r = i - 3328u; b = r >> 2; tile = r & 3;  }

        // wait on immediate predecessor stage, same batch
        if (stage > 0) {
            const int needs[7] = {0, 4, 8, 8, 16, 8, 8};
            if (tid == 0) {
                volatile int* c = g_cnt + (stage - 1) * B_ + b;
                const int need = needs[stage];
                while (*c < need) __nanosleep(64);
            }
            __threadfence();
            __syncthreads();
        }

        switch (stage) {
            case 0: gemm_core<1, 1, false>(J.s[0], b, tile); break;
            case 1: gemm_core<1, 0, true >(J.s[1], b, tile); break;
            case 2: gemm_core<1, 0, true >(J.s[2], b, tile); break;
            case 3: gemm_core<2, 2, true >(J.s[3], b, tile); break;
            case 4: gemm_core<1, 0, false>(J.s[4], b, tile); break;
            case 5: gemm_core<1, 0, false>(J.s[5], b, tile); break;
            case 6: gemm_core<1, 3, false>(J.s[6], b, tile); break;
        }

        __threadfence();
        __syncthreads();
        if (tid == 0) atomicAdd(&g_cnt[stage * B_ + b], 1);
    }
}

// ===================== tail kernels ===========================================
__global__ void softmax_kernel(float* __restrict__ z, int n)
{
    const int b = blockIdx.x;
    float* row = z + (long)b * n;
    __shared__ float red[256];
    const int tid = threadIdx.x;

    float mx = -1e30f;
    for (int i = tid; i < n; i += 256) mx = fmaxf(mx, row[i]);
    red[tid] = mx; __syncthreads();
    for (int s = 128; s > 0; s >>= 1) {
        if (tid < s) red[tid] = fmaxf(red[tid], red[tid + s]);
        __syncthreads();
    }
    mx = red[0]; __syncthreads();

    float sum = 0.f;
    for (int i = tid; i < n; i += 256) {
        float e = expf(row[i] - mx);
        row[i] = e;
        sum += e;
    }
    red[tid] = sum; __syncthreads();
    for (int s = 128; s > 0; s >>= 1) {
        if (tid < s) red[tid] += red[tid + s];
        __syncthreads();
    }
    float inv = 1.f / red[0];
    for (int i = tid; i < n; i += 256) row[i] *= inv;
}

__global__ void pool_v_kernel(const float* __restrict__ V,
                              const float* __restrict__ a,
                              float* __restrict__ v1)
{
    const int b = blockIdx.y;
    const int warp = threadIdx.x >> 5;
    const int lane = threadIdx.x & 31;
    const int d = blockIdx.x * 8 + warp;
    const float4* vr = reinterpret_cast<const float4*>(V + ((long)b * D_ + d) * M_);
    const float4* ar = reinterpret_cast<const float4*>(a + (long)b * M_);
    float acc = 0.f;
#pragma unroll
    for (int i = 0; i < M_ / 128; i++) {
        float4 v = vr[i * 32 + lane];
        float4 w = ar[i * 32 + lane];
        acc += v.x * w.x + v.y * w.y + v.z * w.z + v.w * w.w;
    }
#pragma unroll
    for (int o = 16; o > 0; o >>= 1) acc += __shfl_down_sync(0xffffffffu, acc, o);
    if (lane == 0) v1[b * D_ + d] = acc;
}

__global__ void pool_q_kernel(const float* __restrict__ Q,
                              const float* __restrict__ a,
                              float* __restrict__ q1)
{
    const int b = blockIdx.x;
    __shared__ float as[L_];
    for (int i = threadIdx.x; i < L_; i += blockDim.x) as[i] = a[b * L_ + i];
    __syncthreads();
    const int d = threadIdx.x;
    const float* qb = Q + (long)b * L_ * D_;
    float acc = 0.f;
#pragma unroll 8
    for (int l = 0; l < L_; l++) acc += as[l] * qb[(long)l * D_ + d];
    q1[b * D_ + d] = acc;
}

__global__ void bcast_kernel(float4* __restrict__ out,
                             const float4* __restrict__ src,
                             int rows)
{
    const long total4 = (long)B_ * rows * (D_ / 4);
    long i = (long)blockIdx.x * blockDim.x + threadIdx.x;
    if (i >= total4) return;
    int d4 = (int)(i % (D_ / 4));
    long br = i / (D_ / 4);
    int b = (int)(br / rows);
    out[i] = __ldg(&src[(long)b * (D_ / 4) + d4]);
}

// ===================== launch =================================================
extern "C" void kernel_launch(void* const* d_in, const int* in_sizes, int n_in,
                              void* d_out, int out_size)
{
    const float* V   = (const float*)d_in[0];  // [B, D, M]
    const float* Q   = (const float*)d_in[1];  // [B, L, D]
    const float* W_b = (const float*)d_in[2];  // [D, D]
    const float* W_v = (const float*)d_in[3];  // [K, D]
    const float* W_q = (const float*)d_in[4];  // [K, D]
    const float* whv = (const float*)d_in[5];  // [K]
    const float* whq = (const float*)d_in[6];  // [K]
    float* out = (float*)d_out;

    bf16 *pWv_h, *pWv_l, *pWq_h, *pWq_l;
    bf16 *pWqQ_h, *pWqQ_l, *pP_h, *pP_l, *pYv_h, *pYv_l;
    bf16 *pWvV_h, *pWvV_l, *pYq_h, *pYq_l, *pR_h, *pR_l;
    float *pWqQ_f, *p_zv, *p_zq, *p_v1, *p_q1;
    void *p_cursor, *p_cnt;
    cudaGetSymbolAddress((void**)&pWv_h, g_Wv_hi);  cudaGetSymbolAddress((void**)&pWv_l, g_Wv_lo);
    cudaGetSymbolAddress((void**)&pWq_h, g_Wq_hi);  cudaGetSymbolAddress((void**)&pWq_l, g_Wq_lo);
    cudaGetSymbolAddress((void**)&pWqQ_h, g_WqQ_hi); cudaGetSymbolAddress((void**)&pWqQ_l, g_WqQ_lo);
    cudaGetSymbolAddress((void**)&pWqQ_f, g_WqQ_f);
    cudaGetSymbolAddress((void**)&pP_h, g_P_hi);    cudaGetSymbolAddress((void**)&pP_l, g_P_lo);
    cudaGetSymbolAddress((void**)&pYv_h, g_Yv_hi);  cudaGetSymbolAddress((void**)&pYv_l, g_Yv_lo);
    cudaGetSymbolAddress((void**)&pWvV_h, g_WvV_hi); cudaGetSymbolAddress((void**)&pWvV_l, g_WvV_lo);
    cudaGetSymbolAddress((void**)&pYq_h, g_Yq_hi);  cudaGetSymbolAddress((void**)&pYq_l, g_Yq_lo);
    cudaGetSymbolAddress((void**)&pR_h, g_R_hi);    cudaGetSymbolAddress((void**)&pR_l, g_R_lo);
    cudaGetSymbolAddress((void**)&p_zv, g_zv);      cudaGetSymbolAddress((void**)&p_zq, g_zq);
    cudaGetSymbolAddress((void**)&p_v1, g_v1);      cudaGetSymbolAddress((void**)&p_q1, g_q1);
    cudaGetSymbolAddress(&p_cursor, g_cursor);
    cudaGetSymbolAddress(&p_cnt, g_cnt);

    cudaFuncSetAttribute(mega_gemm, cudaFuncAttributeMaxDynamicSharedMemorySize, SMEM_SZ);

    // reset scheduler state (graph-capturable memset nodes)
    cudaMemsetAsync(p_cursor, 0, sizeof(unsigned));
    cudaMemsetAsync(p_cnt, 0, 7 * B_ * sizeof(int));

    conv_pad<<<(32 * D_ + 255) / 256, 256>>>(W_v, pWv_h, pWv_l, W_q, pWq_h, pWq_l);

    Jobs J;
    // S0 K1: WqQ = Wq x Q^T : A=Q AN [L][D]; hi/lo + fp32 out
    J.s[0] = { Q, D_, (long)L_ * D_, pWq_h, pWq_l, nullptr, nullptr,
               pWqQ_h, pWqQ_l, pWqQ_f, nullptr, nullptr, L_, D_, 0, 0 };
    // S1 K2: P = WqQ x Q : A=Q TRA (lda=D), Kd=L
    J.s[1] = { Q, D_, (long)L_ * D_, pWqQ_h, pWqQ_l, nullptr, nullptr,
               pP_h, pP_l, nullptr, nullptr, nullptr, D_, L_, (long)32 * L_, 0 };
    // S2 K3: Yv = P x Wb : A=Wb TRA (no batch)
    J.s[2] = { W_b, D_, 0, pP_h, pP_l, nullptr, nullptr,
               pYv_h, pYv_l, nullptr, nullptr, nullptr, D_, D_, (long)32 * D_, 0 };
    // S3 K45: A=V TRA (lda=M); B0=Wv -> WvV; B1=Yv -> Tv (fused logits_v)
    J.s[3] = { V, M_, (long)D_ * M_, pWv_h, pWv_l, pYv_h, pYv_l,
               pWvV_h, pWvV_l, nullptr, whv, p_zv, M_, D_, 0, (long)32 * D_ };
    // S4 K6: Yq = WvV x V^T : A=V AN [D][M], Kd=M
    J.s[4] = { V, M_, (long)D_ * M_, pWvV_h, pWvV_l, nullptr, nullptr,
               pYq_h, pYq_l, nullptr, nullptr, nullptr, D_, M_, (long)32 * M_, 0 };
    // S5 K7: R = Yq x Wb^T : A=Wb AN (no batch)
    J.s[5] = { W_b, D_, 0, pYq_h, pYq_l, nullptr, nullptr,
               pR_h, pR_l, nullptr, nullptr, nullptr, D_, D_, (long)32 * D_, 0 };
    // S6 K8: Tq = R x Q^T : A=Q AN; X=WqQ_f (fused logits_q)
    J.s[6] = { Q, D_, (long)L_ * D_, pR_h, pR_l, nullptr, nullptr,
               nullptr, nullptr, pWqQ_f, whq, p_zq, L_, D_, (long)32 * D_, 0 };

    mega_gemm<<<740, 128, SMEM_SZ>>>(J);

    // softmax
    softmax_kernel<<<B_, 256>>>(p_zv, M_);
    softmax_kernel<<<B_, 256>>>(p_zq, L_);

    // pooled vectors
    {
        dim3 grid(D_ / 8, B_);
        pool_v_kernel<<<grid, 256>>>(V, p_zv, p_v1);
    }
    pool_q_kernel<<<B_, 512>>>(Q, p_zq, p_q1);

    // broadcast outputs: v [B,M,D] then q [B,L,D]
    {
        long n4v = (long)B_ * M_ * (D_ / 4);
        bcast_kernel<<<(unsigned)((n4v + 255) / 256), 256>>>(
            (float4*)out, (const float4*)p_v1, M_);
        long n4q = (long)B_ * L_ * (D_ / 4);
        float* out_q = out + (long)B_ * M_ * D_;
        bcast_kernel<<<(unsigned)((n4q + 255) / 256), 256>>>(
            (float4*)out_q, (const float4*)p_q1, L_);
    }
}

// round 12
// speedup vs baseline: 1.0113x; 1.0113x over previous
#include <cuda_runtime.h>
#include <cuda_bf16.h>
#include <math.h>
#include <stdint.h>

// Problem dims (fixed)
#define B_ 64
#define D_ 512
#define M_ 1024
#define L_ 256
#define KK_ 30

typedef __nv_bfloat16 bf16;

// ===================== device scratch (split partials: [2] pairs) =============
#define PL ((long)B_ * 32 * L_)
#define PD ((long)B_ * 32 * D_)
__device__ bf16 g_Wv_hi[32 * D_];
__device__ bf16 g_Wv_lo[32 * D_];
__device__ bf16 g_Wq_hi[32 * D_];
__device__ bf16 g_Wq_lo[32 * D_];
__device__ bf16 g_WqQ_hi[2 * PL];
__device__ bf16 g_WqQ_lo[2 * PL];
__device__ float g_WqQ_f[2 * PL];
__device__ bf16 g_P_hi[2 * PD];
__device__ bf16 g_P_lo[2 * PD];
__device__ bf16 g_Yv_hi[2 * PD];
__device__ bf16 g_Yv_lo[2 * PD];
__device__ bf16 g_WvV_hi[(long)B_ * 32 * M_];
__device__ bf16 g_WvV_lo[(long)B_ * 32 * M_];
__device__ bf16 g_Yq_hi[2 * PD];
__device__ bf16 g_Yq_lo[2 * PD];
__device__ bf16 g_R_hi[2 * PD];
__device__ bf16 g_R_lo[2 * PD];
__device__ float g_zv[B_ * M_];
__device__ float g_zq[B_ * L_];
__device__ float g_v1[B_ * D_];
__device__ float g_q1[B_ * D_];

// ===================== helpers ================================================
__device__ __forceinline__ uint32_t s2u(const void* p) {
    return (uint32_t)__cvta_generic_to_shared(p);
}
__device__ __forceinline__ void cp16(uint32_t dst, const void* src) {
    asm volatile("cp.async.cg.shared.global [%0], [%1], 16;" :: "r"(dst), "l"(src));
}
__device__ __forceinline__ void cp_commit() { asm volatile("cp.async.commit_group;"); }
__device__ __forceinline__ void cp_wait0()  { asm volatile("cp.async.wait_group 0;"); }

__device__ __forceinline__ void ldsm4(uint32_t* r, uint32_t addr) {
    asm volatile("ldmatrix.sync.aligned.m8n8.x4.shared.b16 {%0,%1,%2,%3}, [%4];"
                 : "=r"(r[0]), "=r"(r[1]), "=r"(r[2]), "=r"(r[3]) : "r"(addr));
}
__device__ __forceinline__ void ldsm4t(uint32_t* r, uint32_t addr) {
    asm volatile("ldmatrix.sync.aligned.m8n8.x4.trans.shared.b16 {%0,%1,%2,%3}, [%4];"
                 : "=r"(r[0]), "=r"(r[1]), "=r"(r[2]), "=r"(r[3]) : "r"(addr));
}
__device__ __forceinline__ void mma_bf(float* d, const uint32_t* a, const uint32_t* b) {
    asm volatile(
        "mma.sync.aligned.m16n8k16.row.col.f32.bf16.bf16.f32 "
        "{%0,%1,%2,%3}, {%4,%5,%6,%7}, {%8,%9}, {%0,%1,%2,%3};"
        : "+f"(d[0]), "+f"(d[1]), "+f"(d[2]), "+f"(d[3])
        : "r"(a[0]), "r"(a[1]), "r"(a[2]), "r"(a[3]), "r"(b[0]), "r"(b[1]));
}
__device__ __forceinline__ void split_bf(float x, bf16& h, bf16& l) {
    h = __float2bfloat16(x);
    l = __float2bfloat16(x - __bfloat162float(h));
}

// smem layout constants (bytes) -- 64-row m-tiles, 128-thread CTAs
#define A_BUF 5120u      // AN: 64 rows x 80B ; TRA: 32 rows x 144B (4608 <= slot)
#define B_BUF 2560u      // 32 x 40 bf16
#define BS_OFF 20480u    // after 4 A slots
#define CST 132          // epilogue staging n-stride (floats)

// ===================== weight pad conversion ==================================
__global__ void conv_pad(const float* __restrict__ Wv, bf16* __restrict__ Vh, bf16* __restrict__ Vl,
                         const float* __restrict__ Wq, bf16* __restrict__ Qh, bf16* __restrict__ Ql)
{
    int idx = blockIdx.x * blockDim.x + threadIdx.x;
    if (idx >= 32 * D_) return;
    int k = idx / D_, d = idx % D_;
    float a = (k < KK_) ? Wv[k * D_ + d] : 0.f;
    float b = (k < KK_) ? Wq[k * D_ + d] : 0.f;
    bf16 h, l;
    split_bf(a, h, l); Vh[idx] = h; Vl[idx] = l;
    split_bf(b, h, l); Qh[idx] = h; Ql[idx] = l;
}

// ===================== HMMA GEMM (R10 pipeline + dual-B split-K) ==============
// Ct[64-row m-tile of Nbig][32] = A(fp32, on-the-fly bf16 hi/lo) x sum_nb S_nb^T
// NBT B operands; accumulator map: NBT==3 -> {0,1,1}, else all into acc0.
struct GJob {
    const float* A;                      // fp32 big operand
    int lda; long sA;
    const bf16 *Bh0, *Bl0, *Bh1, *Bl1, *Bh2, *Bl2;
    long sB0, sB1, sB2;
    bf16 *Ch, *Cl;                       // out [b][32][Nbig] (+ split*partC)
    float* Cf;                           // EPI1: fp32 out base; EPI3: X0
    const float* Cf2;                    // EPI3: X1 (second partial)
    const float* w;                      // logits weights (EPI 2/3)
    float* z;                            // logits out [b][Nbig]
    int Nbig, Kd, nsplit;
    long partC;
};

// EPI: 0 = hi/lo out; 1 = hi/lo + fp32 out; 2 = (NBT=3, 2 accs) hi/lo of acc0 +
//      fused logits(acc0+acc1); 3 = logits(acc0 + X0 + X1), no C out
template<int NBT, int EPI, bool TRA>
__global__ void __launch_bounds__(128) tc_gemm(GJob j)
{
    constexpr int NACC = (EPI == 2) ? 2 : 1;
    extern __shared__ char smem[];
    const uint32_t sb = s2u(smem);
    float* smw = (float*)(smem + BS_OFF + NBT * 4 * B_BUF);

    const int tid = threadIdx.x;
    const int w = tid >> 5, lane = tid & 31;
    const int b = blockIdx.y;
    const int split = blockIdx.z;
    const int m0 = blockIdx.x * 64;

    const float* Ab = j.A + (long)b * j.sA;
    const bf16* Bh[3];
    const bf16* Bl[3];
    Bh[0] = j.Bh0 + (long)b * j.sB0;  Bl[0] = j.Bl0 + (long)b * j.sB0;
    if (NBT >= 2) { Bh[1] = j.Bh1 + (long)b * j.sB1;  Bl[1] = j.Bl1 + (long)b * j.sB1; }
    if (NBT >= 3) { Bh[2] = j.Bh2 + (long)b * j.sB2;  Bl[2] = j.Bl2 + (long)b * j.sB2; }

    if (EPI >= 2 && tid < KK_) smw[tid] = j.w[tid];

    // A gmem addressing (16 floats per thread per 32-k tile)
    const float* aptr = TRA
        ? (Ab + (long)(tid >> 2) * j.lda + m0 + (tid & 3) * 16)
        : (Ab + (long)(m0 + (tid >> 1)) * j.lda + (tid & 1) * 16);
    const uint32_t aSts = TRA ? (uint32_t)((tid >> 2) * 144 + (tid & 3) * 32)
                              : (uint32_t)((tid >> 1) * 80 + (tid & 1) * 32);

    // B staging indices: 32 rows x 4 cols of 16B per array
    const int br = tid >> 2, bc = tid & 3;

    const int range = j.Kd / 32 / j.nsplit;
    const int t0 = split * range;
    float4 fr[4];

    auto loadA = [&](int t) {
        const float* p = TRA ? (aptr + (long)t * 32 * j.lda) : (aptr + t * 32);
        fr[0] = *(const float4*)p;
        fr[1] = *(const float4*)(p + 4);
        fr[2] = *(const float4*)(p + 8);
        fr[3] = *(const float4*)(p + 12);
    };
    auto stsA = [&](int s) {
        uint32_t hp[8], lp[8];
        const float* f = (const float*)fr;
#pragma unroll
        for (int i = 0; i < 8; i++) {
            bf16 h0, l0, h1, l1;
            split_bf(f[2 * i], h0, l0);
            split_bf(f[2 * i + 1], h1, l1);
            hp[i] = (uint32_t)*(uint16_t*)&h0 | ((uint32_t)*(uint16_t*)&h1 << 16);
            lp[i] = (uint32_t)*(uint16_t*)&l0 | ((uint32_t)*(uint16_t*)&l1 << 16);
        }
        char* d0 = smem + (s * 2 + 0) * A_BUF + aSts;
        char* d1 = smem + (s * 2 + 1) * A_BUF + aSts;
        *(uint4*)d0        = make_uint4(hp[0], hp[1], hp[2], hp[3]);
        *(uint4*)(d0 + 16) = make_uint4(hp[4], hp[5], hp[6], hp[7]);
        *(uint4*)d1        = make_uint4(lp[0], lp[1], lp[2], lp[3]);
        *(uint4*)(d1 + 16) = make_uint4(lp[4], lp[5], lp[6], lp[7]);
    };
    auto stageB = [&](int t) {
        const int s = t & 1;
#pragma unroll
        for (int nb = 0; nb < NBT; nb++) {
            uint32_t base = sb + BS_OFF + (uint32_t)(((s * NBT + nb) * 2) * B_BUF)
                          + br * 80 + bc * 16;
            long off = (long)br * j.Kd + t * 32 + bc * 8;
            cp16(base,         Bh[nb] + off);
            cp16(base + B_BUF, Bl[nb] + off);
        }
        cp_commit();
    };

    // ldmatrix lane addressing
    const uint32_t aLane = TRA
        ? (uint32_t)((((lane & 7) + 8 * (lane >> 4)) * 144) + (w * 16 + ((lane >> 3) & 1) * 8) * 2)
        : (uint32_t)((w * 16 + (lane & 15)) * 80 + (lane >> 4) * 16);
    const uint32_t aKs = TRA ? 2304u : 32u;
    const uint32_t bLaneRow = (uint32_t)((((lane >> 4) & 1) * 8 + (lane & 7)) * 80
                                         + ((lane >> 3) & 1) * 16);

    float acc[NACC][4][4];
#pragma unroll
    for (int na = 0; na < NACC; na++)
#pragma unroll
        for (int nt = 0; nt < 4; nt++)
#pragma unroll
            for (int r = 0; r < 4; r++) acc[na][nt][r] = 0.f;

    stageB(t0);
    loadA(t0);

    for (int tt = 0; tt < range; tt++) {
        const int t = t0 + tt;
        const int s = t & 1;
        cp_wait0();
        __syncthreads();

        stsA(s);
        if (tt + 1 < range) { stageB(t + 1); loadA(t + 1); }
        __syncthreads();

        const uint32_t aH = sb + (uint32_t)((s * 2 + 0) * A_BUF) + aLane;
        const uint32_t aL = aH + A_BUF;

#pragma unroll
        for (int ks = 0; ks < 2; ks++) {
            uint32_t ah[4], al[4];
            if (TRA) { ldsm4t(ah, aH + ks * aKs); ldsm4t(al, aL + ks * aKs); }
            else     { ldsm4 (ah, aH + ks * aKs); ldsm4 (al, aL + ks * aKs); }
#pragma unroll
            for (int nb = 0; nb < NBT; nb++) {
                constexpr int AM3[3] = {0, 1, 1};
                const int na = (NBT == 3) ? AM3[nb] : 0;
#pragma unroll
                for (int p = 0; p < 2; p++) {
                    uint32_t bbase = sb + BS_OFF + (uint32_t)(((s * NBT + nb) * 2) * B_BUF)
                        + (uint32_t)(p * 16 * 80) + bLaneRow + ks * 32;
                    uint32_t bh[4], bl[4];
                    ldsm4(bh, bbase);
                    ldsm4(bl, bbase + B_BUF);
                    mma_bf(acc[na][2 * p],     ah, &bh[0]);
                    mma_bf(acc[na][2 * p],     ah, &bl[0]);
                    mma_bf(acc[na][2 * p],     al, &bh[0]);
                    mma_bf(acc[na][2 * p + 1], ah, &bh[2]);
                    mma_bf(acc[na][2 * p + 1], ah, &bl[2]);
                    mma_bf(acc[na][2 * p + 1], al, &bh[2]);
                }
            }
        }
    }

    // ---------------- epilogue --------------------------------------------
    __syncthreads();
    float* Cs = (float*)smem;
    {
        const int g = lane >> 2, cc = lane & 3;
        const int m_l = w * 16 + g;
#pragma unroll
        for (int na = 0; na < NACC; na++) {
            float* C_ = Cs + na * 32 * CST;
#pragma unroll
            for (int nt = 0; nt < 4; nt++) {
                int n0 = nt * 8 + cc * 2;
                C_[(n0 + 0) * CST + m_l]     = acc[na][nt][0];
                C_[(n0 + 1) * CST + m_l]     = acc[na][nt][1];
                C_[(n0 + 0) * CST + m_l + 8] = acc[na][nt][2];
                C_[(n0 + 1) * CST + m_l + 8] = acc[na][nt][3];
            }
        }
    }
    __syncthreads();

    if (EPI != 3) {
        bf16* Coh = j.Ch + (long)split * j.partC;
        bf16* Col = j.Cl + (long)split * j.partC;
        float* Cof = (EPI == 1) ? (j.Cf + (long)split * j.partC) : nullptr;
#pragma unroll
        for (int it = 0; it < 4; it++) {
            int q = tid + it * 128;
            int n = q >> 4, m4 = (q & 15) * 4;
            float4 v = *(float4*)&Cs[n * CST + m4];
            bf16 h0, l0, h1, l1, h2, l2, h3, l3;
            split_bf(v.x, h0, l0); split_bf(v.y, h1, l1);
            split_bf(v.z, h2, l2); split_bf(v.w, h3, l3);
            long o = ((long)b * 32 + n) * j.Nbig + m0 + m4;
            *(uint2*)(Coh + o) = make_uint2(
                ((uint32_t)*(uint16_t*)&h0) | ((uint32_t)*(uint16_t*)&h1 << 16),
                ((uint32_t)*(uint16_t*)&h2) | ((uint32_t)*(uint16_t*)&h3 << 16));
            *(uint2*)(Col + o) = make_uint2(
                ((uint32_t)*(uint16_t*)&l0) | ((uint32_t)*(uint16_t*)&l1 << 16),
                ((uint32_t)*(uint16_t*)&l2) | ((uint32_t)*(uint16_t*)&l3 << 16));
            if (EPI == 1) *(float4*)(Cof + o) = v;
        }
    }
    if (EPI == 2) {
        if (tid < 64) {
            float zacc = 0.f;
#pragma unroll
            for (int k = 0; k < KK_; k++)
                zacc += smw[k] * tanhf(Cs[k * CST + tid] + Cs[(32 + k) * CST + tid]);
            j.z[(long)b * j.Nbig + m0 + tid] = zacc;
        }
    }
    if (EPI == 3) {
        if (tid < 64) {
            const float* X0 = j.Cf  + (long)b * 32 * j.Nbig + m0 + tid;
            const float* X1 = j.Cf2 + (long)b * 32 * j.Nbig + m0 + tid;
            float zacc = 0.f;
#pragma unroll
            for (int k = 0; k < KK_; k++)
                zacc += smw[k] * tanhf(Cs[k * CST + tid]
                                       + X0[(long)k * j.Nbig] + X1[(long)k * j.Nbig]);
            j.z[(long)b * j.Nbig + m0 + tid] = zacc;
        }
    }
}

// ===================== tail kernels ===========================================
// one launch: blocks [0,64) -> zv rows (n=M), [64,128) -> zq rows (n=L)
__global__ void softmax2_kernel(float* __restrict__ zv, float* __restrict__ zq)
{
    const int blk = blockIdx.x;
    const int n = (blk < B_) ? M_ : L_;
    float* row = (blk < B_) ? (zv + (long)blk * M_) : (zq + (long)(blk - B_) * L_);
    __shared__ float red[256];
    const int tid = threadIdx.x;

    float mx = -1e30f;
    for (int i = tid; i < n; i += 256) mx = fmaxf(mx, row[i]);
    red[tid] = mx; __syncthreads();
    for (int s = 128; s > 0; s >>= 1) {
        if (tid < s) red[tid] = fmaxf(red[tid], red[tid + s]);
        __syncthreads();
    }
    mx = red[0]; __syncthreads();

    float sum = 0.f;
    for (int i = tid; i < n; i += 256) {
        float e = expf(row[i] - mx);
        row[i] = e;
        sum += e;
    }
    red[tid] = sum; __syncthreads();
    for (int s = 128; s > 0; s >>= 1) {
        if (tid < s) red[tid] += red[tid + s];
        __syncthreads();
    }
    float inv = 1.f / red[0];
    for (int i = tid; i < n; i += 256) row[i] *= inv;
}

__global__ void pool_v_kernel(const float* __restrict__ V,
                              const float* __restrict__ a,
                              float* __restrict__ v1)
{
    const int b = blockIdx.y;
    const int warp = threadIdx.x >> 5;
    const int lane = threadIdx.x & 31;
    const int d = blockIdx.x * 8 + warp;
    const float4* vr = reinterpret_cast<const float4*>(V + ((long)b * D_ + d) * M_);
    const float4* ar = reinterpret_cast<const float4*>(a + (long)b * M_);
    float acc = 0.f;
#pragma unroll
    for (int i = 0; i < M_ / 128; i++) {
        float4 v = vr[i * 32 + lane];
        float4 w = ar[i * 32 + lane];
        acc += v.x * w.x + v.y * w.y + v.z * w.z + v.w * w.w;
    }
#pragma unroll
    for (int o = 16; o > 0; o >>= 1) acc += __shfl_down_sync(0xffffffffu, acc, o);
    if (lane == 0) v1[b * D_ + d] = acc;
}

__global__ void pool_q_kernel(const float* __restrict__ Q,
                              const float* __restrict__ a,
                              float* __restrict__ q1)
{
    const int b = blockIdx.x;
    __shared__ float as[L_];
    for (int i = threadIdx.x; i < L_; i += blockDim.x) as[i] = a[b * L_ + i];
    __syncthreads();
    const int d = threadIdx.x;
    const float* qb = Q + (long)b * L_ * D_;
    float acc = 0.f;
#pragma unroll 8
    for (int l = 0; l < L_; l++) acc += as[l] * qb[(long)l * D_ + d];
    q1[b * D_ + d] = acc;
}

// single launch: writes v region [B,M,D] then q region [B,L,D]
__global__ void bcast_all(float4* __restrict__ out,
                          const float4* __restrict__ v1,
                          const float4* __restrict__ q1)
{
    const long nv4 = (long)B_ * M_ * (D_ / 4);
    const long nq4 = (long)B_ * L_ * (D_ / 4);
    long i = (long)blockIdx.x * blockDim.x + threadIdx.x;
    if (i < nv4) {
        int d4 = (int)(i % (D_ / 4));
        int b = (int)((i / (D_ / 4)) / M_);
        out[i] = __ldg(&v1[(long)b * (D_ / 4) + d4]);
    } else if (i < nv4 + nq4) {
        long k = i - nv4;
        int d4 = (int)(k % (D_ / 4));
        int b = (int)((k / (D_ / 4)) / L_);
        out[i] = __ldg(&q1[(long)b * (D_ / 4) + d4]);
    }
}

// ===================== launch =================================================
extern "C" void kernel_launch(void* const* d_in, const int* in_sizes, int n_in,
                              void* d_out, int out_size)
{
    const float* V   = (const float*)d_in[0];  // [B, D, M]
    const float* Q   = (const float*)d_in[1];  // [B, L, D]
    const float* W_b = (const float*)d_in[2];  // [D, D]
    const float* W_v = (const float*)d_in[3];  // [K, D]
    const float* W_q = (const float*)d_in[4];  // [K, D]
    const float* whv = (const float*)d_in[5];  // [K]
    const float* whq = (const float*)d_in[6];  // [K]
    float* out = (float*)d_out;

    bf16 *pWv_h, *pWv_l, *pWq_h, *pWq_l;
    bf16 *pWqQ_h, *pWqQ_l, *pP_h, *pP_l, *pYv_h, *pYv_l;
    bf16 *pWvV_h, *pWvV_l, *pYq_h, *pYq_l, *pR_h, *pR_l;
    float *pWqQ_f, *p_zv, *p_zq, *p_v1, *p_q1;
    cudaGetSymbolAddress((void**)&pWv_h, g_Wv_hi);  cudaGetSymbolAddress((void**)&pWv_l, g_Wv_lo);
    cudaGetSymbolAddress((void**)&pWq_h, g_Wq_hi);  cudaGetSymbolAddress((void**)&pWq_l, g_Wq_lo);
    cudaGetSymbolAddress((void**)&pWqQ_h, g_WqQ_hi); cudaGetSymbolAddress((void**)&pWqQ_l, g_WqQ_lo);
    cudaGetSymbolAddress((void**)&pWqQ_f, g_WqQ_f);
    cudaGetSymbolAddress((void**)&pP_h, g_P_hi);    cudaGetSymbolAddress((void**)&pP_l, g_P_lo);
    cudaGetSymbolAddress((void**)&pYv_h, g_Yv_hi);  cudaGetSymbolAddress((void**)&pYv_l, g_Yv_lo);
    cudaGetSymbolAddress((void**)&pWvV_h, g_WvV_hi); cudaGetSymbolAddress((void**)&pWvV_l, g_WvV_lo);
    cudaGetSymbolAddress((void**)&pYq_h, g_Yq_hi);  cudaGetSymbolAddress((void**)&pYq_l, g_Yq_lo);
    cudaGetSymbolAddress((void**)&pR_h, g_R_hi);    cudaGetSymbolAddress((void**)&pR_l, g_R_lo);
    cudaGetSymbolAddress((void**)&p_zv, g_zv);      cudaGetSymbolAddress((void**)&p_zq, g_zq);
    cudaGetSymbolAddress((void**)&p_v1, g_v1);      cudaGetSymbolAddress((void**)&p_q1, g_q1);

    const int SM1 = (int)(BS_OFF + 1 * 4 * B_BUF + 128);  // 30848
    const int SM2 = (int)(BS_OFF + 2 * 4 * B_BUF + 128);  // 41088
    const int SM3 = (int)(BS_OFF + 3 * 4 * B_BUF + 128);  // 51328
    cudaFuncSetAttribute(tc_gemm<1, 1, false>, cudaFuncAttributeMaxDynamicSharedMemorySize, SM1);
    cudaFuncSetAttribute(tc_gemm<2, 0, true>,  cudaFuncAttributeMaxDynamicSharedMemorySize, SM2);
    cudaFuncSetAttribute(tc_gemm<3, 2, true>,  cudaFuncAttributeMaxDynamicSharedMemorySize, SM3);
    cudaFuncSetAttribute(tc_gemm<1, 0, false>, cudaFuncAttributeMaxDynamicSharedMemorySize, SM1);
    cudaFuncSetAttribute(tc_gemm<2, 0, false>, cudaFuncAttributeMaxDynamicSharedMemorySize, SM2);
    cudaFuncSetAttribute(tc_gemm<2, 3, false>, cudaFuncAttributeMaxDynamicSharedMemorySize, SM2);

    conv_pad<<<(32 * D_ + 255) / 256, 256>>>(W_v, pWv_h, pWv_l, W_q, pWq_h, pWq_l);

    const long sQ = (long)L_ * D_;
    const long sV = (long)D_ * M_;
    GJob j;

    // K1 (split 2): WqQ = Wq x Q^T : A=Q AN; hi/lo + fp32 per split
    j = { Q, D_, sQ, pWq_h, pWq_l, nullptr, nullptr, nullptr, nullptr, 0, 0, 0,
          pWqQ_h, pWqQ_l, pWqQ_f, nullptr, nullptr, nullptr, L_, D_, 2, PL };
    tc_gemm<1, 1, false><<<dim3(L_ / 64, B_, 2), 128, SM1>>>(j);

    // K2 (split 2, dual-B): P = (WqQ0+WqQ1) x Q : A=Q TRA, Kd=L
    j = { Q, D_, sQ, pWqQ_h, pWqQ_l, pWqQ_h + PL, pWqQ_l + PL, nullptr, nullptr,
          (long)32 * L_, (long)32 * L_, 0,
          pP_h, pP_l, nullptr, nullptr, nullptr, nullptr, D_, L_, 2, PD };
    tc_gemm<2, 0, true><<<dim3(D_ / 64, B_, 2), 128, SM2>>>(j);

    // K3 (split 2, dual-B): Yv = (P0+P1) x Wb : A=Wb TRA (no batch)
    j = { W_b, D_, 0, pP_h, pP_l, pP_h + PD, pP_l + PD, nullptr, nullptr,
          (long)32 * D_, (long)32 * D_, 0,
          pYv_h, pYv_l, nullptr, nullptr, nullptr, nullptr, D_, D_, 2, PD };
    tc_gemm<2, 0, true><<<dim3(D_ / 64, B_, 2), 128, SM2>>>(j);

    // K45 (unsplit, NBT=3): A=V TRA; B0=Wv -> WvV (acc0); B1,B2=Yv pair -> Tv (acc1);
    //      fused logits_v
    j = { V, M_, sV, pWv_h, pWv_l, pYv_h, pYv_l, pYv_h + PD, pYv_l + PD,
          0, (long)32 * D_, (long)32 * D_,
          pWvV_h, pWvV_l, nullptr, nullptr, whv, p_zv, M_, D_, 1, 0 };
    tc_gemm<3, 2, true><<<dim3(M_ / 64, B_, 1), 128, SM3>>>(j);

    // K6 (split 2): Yq = WvV x V^T : A=V AN, Kd=M
    j = { V, M_, sV, pWvV_h, pWvV_l, nullptr, nullptr, nullptr, nullptr,
          (long)32 * M_, 0, 0,
          pYq_h, pYq_l, nullptr, nullptr, nullptr, nullptr, D_, M_, 2, PD };
    tc_gemm<1, 0, false><<<dim3(D_ / 64, B_, 2), 128, SM1>>>(j);

    // K7 (split 2, dual-B): R = (Yq0+Yq1) x Wb^T : A=Wb AN (no batch)
    j = { W_b, D_, 0, pYq_h, pYq_l, pYq_h + PD, pYq_l + PD, nullptr, nullptr,
          (long)32 * D_, (long)32 * D_, 0,
          pR_h, pR_l, nullptr, nullptr, nullptr, nullptr, D_, D_, 2, PD };
    tc_gemm<2, 0, false><<<dim3(D_ / 64, B_, 2), 128, SM2>>>(j);

    // K8 (unsplit, dual-B): Tq = (R0+R1) x Q^T : A=Q AN; X = WqQ_f0 + WqQ_f1
    j = { Q, D_, sQ, pR_h, pR_l, pR_h + PD, pR_l + PD, nullptr, nullptr,
          (long)32 * D_, (long)32 * D_, 0,
          nullptr, nullptr, pWqQ_f, pWqQ_f + PL, whq, p_zq, L_, D_, 1, 0 };
    tc_gemm<2, 3, false><<<dim3(L_ / 64, B_, 1), 128, SM2>>>(j);

    // fused softmax (zv + zq in one launch)
    softmax2_kernel<<<2 * B_, 256>>>(p_zv, p_zq);

    // pooled vectors
    {
        dim3 grid(D_ / 8, B_);
        pool_v_kernel<<<grid, 256>>>(V, p_zv, p_v1);
    }
    pool_q_kernel<<<B_, 512>>>(Q, p_zq, p_q1);

    // broadcast both outputs in one launch
    {
        long n4 = (long)B_ * (M_ + L_) * (D_ / 4);
        bcast_all<<<(unsigned)((n4 + 255) / 256), 256>>>(
            (float4*)out, (const float4*)p_v1, (const float4*)p_q1);
    }
}

// round 13
// speedup vs baseline: 1.0378x; 1.0262x over previous
#include <cuda_runtime.h>
#include <cuda_bf16.h>
#include <math.h>
#include <stdint.h>

// Problem dims (fixed)
#define B_ 64
#define D_ 512
#define M_ 1024
#define L_ 256
#define KK_ 30

typedef __nv_bfloat16 bf16;

// ===================== device scratch =========================================
__device__ bf16 g_Wv_hi[32 * D_];
__device__ bf16 g_Wv_lo[32 * D_];
__device__ bf16 g_Wq_hi[32 * D_];
__device__ bf16 g_Wq_lo[32 * D_];
__device__ bf16 g_WqQ_hi[(long)B_ * 32 * L_];
__device__ bf16 g_WqQ_lo[(long)B_ * 32 * L_];
__device__ float g_WqQ_f[(long)B_ * 32 * L_];
__device__ bf16 g_P_hi[(long)B_ * 32 * D_];
__device__ bf16 g_P_lo[(long)B_ * 32 * D_];
__device__ bf16 g_Yv_hi[(long)B_ * 32 * D_];
__device__ bf16 g_Yv_lo[(long)B_ * 32 * D_];
__device__ bf16 g_WvV_hi[(long)B_ * 32 * M_];
__device__ bf16 g_WvV_lo[(long)B_ * 32 * M_];
__device__ bf16 g_Yq_hi[(long)B_ * 32 * D_];
__device__ bf16 g_Yq_lo[(long)B_ * 32 * D_];
__device__ bf16 g_R_hi[(long)B_ * 32 * D_];
__device__ bf16 g_R_lo[(long)B_ * 32 * D_];
__device__ float g_zv[B_ * M_];
__device__ float g_zq[B_ * L_];
__device__ float g_v1[B_ * D_];
__device__ float g_q1[B_ * D_];

// ===================== helpers ================================================
__device__ __forceinline__ uint32_t s2u(const void* p) {
    return (uint32_t)__cvta_generic_to_shared(p);
}
__device__ __forceinline__ void cp16(uint32_t dst, const void* src) {
    asm volatile("cp.async.cg.shared.global [%0], [%1], 16;" :: "r"(dst), "l"(src));
}
__device__ __forceinline__ void cp_commit() { asm volatile("cp.async.commit_group;"); }
__device__ __forceinline__ void cp_wait0()  { asm volatile("cp.async.wait_group 0;"); }

__device__ __forceinline__ void ldsm4(uint32_t* r, uint32_t addr) {
    asm volatile("ldmatrix.sync.aligned.m8n8.x4.shared.b16 {%0,%1,%2,%3}, [%4];"
                 : "=r"(r[0]), "=r"(r[1]), "=r"(r[2]), "=r"(r[3]) : "r"(addr));
}
__device__ __forceinline__ void ldsm4t(uint32_t* r, uint32_t addr) {
    asm volatile("ldmatrix.sync.aligned.m8n8.x4.trans.shared.b16 {%0,%1,%2,%3}, [%4];"
                 : "=r"(r[0]), "=r"(r[1]), "=r"(r[2]), "=r"(r[3]) : "r"(addr));
}
__device__ __forceinline__ void mma_bf(float* d, const uint32_t* a, const uint32_t* b) {
    asm volatile(
        "mma.sync.aligned.m16n8k16.row.col.f32.bf16.bf16.f32 "
        "{%0,%1,%2,%3}, {%4,%5,%6,%7}, {%8,%9}, {%0,%1,%2,%3};"
        : "+f"(d[0]), "+f"(d[1]), "+f"(d[2]), "+f"(d[3])
        : "r"(a[0]), "r"(a[1]), "r"(a[2]), "r"(a[3]), "r"(b[0]), "r"(b[1]));
}
__device__ __forceinline__ void split_bf(float x, bf16& h, bf16& l) {
    h = __float2bfloat16(x);
    l = __float2bfloat16(x - __bfloat162float(h));
}

// smem layout constants (bytes) -- 64-row m-tiles, 128-thread CTAs
#define A_BUF 5120u      // AN: 64 rows x 80B ; TRA: 32 rows x 144B (4608 <= slot)
#define B_BUF 2560u      // 32 x 40 bf16
#define BS_OFF 20480u    // after 4 A slots
#define CST 132          // epilogue staging n-stride (floats)

// ===================== weight pad conversion ==================================
__global__ void conv_pad(const float* __restrict__ Wv, bf16* __restrict__ Vh, bf16* __restrict__ Vl,
                         const float* __restrict__ Wq, bf16* __restrict__ Qh, bf16* __restrict__ Ql)
{
    int idx = blockIdx.x * blockDim.x + threadIdx.x;
    if (idx >= 32 * D_) return;
    int k = idx / D_, d = idx % D_;
    float a = (k < KK_) ? Wv[k * D_ + d] : 0.f;
    float b = (k < KK_) ? Wq[k * D_ + d] : 0.f;
    bf16 h, l;
    split_bf(a, h, l); Vh[idx] = h; Vl[idx] = l;
    split_bf(b, h, l); Qh[idx] = h; Ql[idx] = l;
}

// ===================== HMMA GEMM (R10 pipeline, 64-row tiles) ==================
// Ct[64-row m-tile of Nbig][32] = A(fp32, converted on the fly) x S[32,Kd]^T
struct GJob {
    const float* A;                      // fp32 big operand
    int lda; long sA;
    const bf16 *B0h, *B0l, *B1h, *B1l;   // small operands [32][Kd] bf16
    bf16 *Ch, *Cl;                       // out [b][32][Nbig]
    float* Cf;                           // EPI1: fp32 out; EPI3: fp32 X in
    const float* w;                      // logits weights (EPI 2/3)
    float* z;                            // logits out [b][Nbig]
    int Nbig, Kd;
    long sB0, sB1;
};

// EPI: 0 = hi/lo out; 1 = hi/lo + fp32 out; 2 = (NB=2) hi/lo of acc0 + fused
//      logits(acc0+acc1); 3 = logits(acc0 + fp32 X), no C out
template<int NB, int EPI, bool TRA>
__global__ void __launch_bounds__(128) tc_gemm(GJob j)
{
    extern __shared__ char smem[];
    const uint32_t sb = s2u(smem);
    float* smw = (float*)(smem + BS_OFF + NB * 4 * B_BUF);

    const int tid = threadIdx.x;
    const int w = tid >> 5, lane = tid & 31;
    const int b = blockIdx.y;
    const int m0 = blockIdx.x * 64;

    const float* Ab = j.A + (long)b * j.sA;
    const bf16* Bb[2][2];
    Bb[0][0] = j.B0h + (long)b * j.sB0;
    Bb[0][1] = j.B0l + (long)b * j.sB0;
    if (NB == 2) {
        Bb[1][0] = j.B1h + (long)b * j.sB1;
        Bb[1][1] = j.B1l + (long)b * j.sB1;
    }

    if (EPI >= 2 && tid < KK_) smw[tid] = j.w[tid];

    // A gmem addressing (16 floats per thread per 32-k tile)
    const float* aptr = TRA
        ? (Ab + (long)(tid >> 2) * j.lda + m0 + (tid & 3) * 16)
        : (Ab + (long)(m0 + (tid >> 1)) * j.lda + (tid & 1) * 16);
    const uint32_t aSts = TRA ? (uint32_t)((tid >> 2) * 144 + (tid & 3) * 32)
                              : (uint32_t)((tid >> 1) * 80 + (tid & 1) * 32);

    // B staging indices: 32 rows x 4 cols of 16B, both hl per thread
    const int br = tid >> 2, bc = tid & 3;

    const int T = j.Kd / 32;
    float4 fr[4];

    auto loadA = [&](int t) {
        const float* p = TRA ? (aptr + (long)t * 32 * j.lda) : (aptr + t * 32);
        fr[0] = *(const float4*)p;
        fr[1] = *(const float4*)(p + 4);
        fr[2] = *(const float4*)(p + 8);
        fr[3] = *(const float4*)(p + 12);
    };
    auto stsA = [&](int s) {
        uint32_t hp[8], lp[8];
        const float* f = (const float*)fr;
#pragma unroll
        for (int i = 0; i < 8; i++) {
            bf16 h0, l0, h1, l1;
            split_bf(f[2 * i], h0, l0);
            split_bf(f[2 * i + 1], h1, l1);
            hp[i] = (uint32_t)*(uint16_t*)&h0 | ((uint32_t)*(uint16_t*)&h1 << 16);
            lp[i] = (uint32_t)*(uint16_t*)&l0 | ((uint32_t)*(uint16_t*)&l1 << 16);
        }
        char* d0 = smem + (s * 2 + 0) * A_BUF + aSts;
        char* d1 = smem + (s * 2 + 1) * A_BUF + aSts;
        *(uint4*)d0        = make_uint4(hp[0], hp[1], hp[2], hp[3]);
        *(uint4*)(d0 + 16) = make_uint4(hp[4], hp[5], hp[6], hp[7]);
        *(uint4*)d1        = make_uint4(lp[0], lp[1], lp[2], lp[3]);
        *(uint4*)(d1 + 16) = make_uint4(lp[4], lp[5], lp[6], lp[7]);
    };
    auto stageB = [&](int t) {
        const int s = t & 1;
#pragma unroll
        for (int nb = 0; nb < NB; nb++)
#pragma unroll
        for (int hl = 0; hl < 2; hl++) {
            uint32_t dst = sb + BS_OFF + (uint32_t)(((s * NB + nb) * 2 + hl) * B_BUF)
                         + br * 80 + bc * 16;
            cp16(dst, Bb[nb][hl] + (long)br * j.Kd + t * 32 + bc * 8);
        }
        cp_commit();
    };

    // ldmatrix lane addressing
    const uint32_t aLane = TRA
        ? (uint32_t)((((lane & 7) + 8 * (lane >> 4)) * 144) + (w * 16 + ((lane >> 3) & 1) * 8) * 2)
        : (uint32_t)((w * 16 + (lane & 15)) * 80 + (lane >> 4) * 16);
    const uint32_t aKs = TRA ? 2304u : 32u;
    const uint32_t bLaneRow = (uint32_t)((((lane >> 4) & 1) * 8 + (lane & 7)) * 80
                                         + ((lane >> 3) & 1) * 16);

    float acc[NB][4][4];
#pragma unroll
    for (int nb = 0; nb < NB; nb++)
#pragma unroll
        for (int nt = 0; nt < 4; nt++)
#pragma unroll
            for (int r = 0; r < 4; r++) acc[nb][nt][r] = 0.f;

    stageB(0);
    loadA(0);

    for (int t = 0; t < T; t++) {
        const int s = t & 1;
        cp_wait0();
        __syncthreads();

        stsA(s);
        if (t + 1 < T) { stageB(t + 1); loadA(t + 1); }
        __syncthreads();

        const uint32_t aH = sb + (uint32_t)((s * 2 + 0) * A_BUF) + aLane;
        const uint32_t aL = aH + A_BUF;

#pragma unroll
        for (int ks = 0; ks < 2; ks++) {
            uint32_t ah[4], al[4];
            if (TRA) { ldsm4t(ah, aH + ks * aKs); ldsm4t(al, aL + ks * aKs); }
            else     { ldsm4 (ah, aH + ks * aKs); ldsm4 (al, aL + ks * aKs); }
#pragma unroll
            for (int nb = 0; nb < NB; nb++) {
#pragma unroll
                for (int p = 0; p < 2; p++) {
                    uint32_t bbase = sb + BS_OFF + (uint32_t)(((s * NB + nb) * 2 + 0) * B_BUF)
                        + (uint32_t)(p * 16 * 80) + bLaneRow + ks * 32;
                    uint32_t bh[4], bl[4];
                    ldsm4(bh, bbase);
                    ldsm4(bl, bbase + B_BUF);
                    mma_bf(acc[nb][2 * p],     ah, &bh[0]);
                    mma_bf(acc[nb][2 * p],     ah, &bl[0]);
                    mma_bf(acc[nb][2 * p],     al, &bh[0]);
                    mma_bf(acc[nb][2 * p + 1], ah, &bh[2]);
                    mma_bf(acc[nb][2 * p + 1], ah, &bl[2]);
                    mma_bf(acc[nb][2 * p + 1], al, &bh[2]);
                }
            }
        }
    }

    // ---------------- epilogue: stage accs in smem (reuses A region) ---------
    __syncthreads();
    float* Cs = (float*)smem;
    {
        const int g = lane >> 2, cc = lane & 3;
        const int m_l = w * 16 + g;          // 0..63
#pragma unroll
        for (int nb = 0; nb < NB; nb++) {
            float* C_ = Cs + nb * 32 * CST;
#pragma unroll
            for (int nt = 0; nt < 4; nt++) {
                int n0 = nt * 8 + cc * 2;
                C_[(n0 + 0) * CST + m_l]     = acc[nb][nt][0];
                C_[(n0 + 1) * CST + m_l]     = acc[nb][nt][1];
                C_[(n0 + 0) * CST + m_l + 8] = acc[nb][nt][2];
                C_[(n0 + 1) * CST + m_l + 8] = acc[nb][nt][3];
            }
        }
    }
    __syncthreads();

    if (EPI != 3) {
        // write acc0 tile: 32 n x 64 m = 512 float4, 128 threads x 4 iters
#pragma unroll
        for (int it = 0; it < 4; it++) {
            int q = tid + it * 128;
            int n = q >> 4, m4 = (q & 15) * 4;
            float4 v = *(float4*)&Cs[n * CST + m4];
            bf16 h0, l0, h1, l1, h2, l2, h3, l3;
            split_bf(v.x, h0, l0); split_bf(v.y, h1, l1);
            split_bf(v.z, h2, l2); split_bf(v.w, h3, l3);
            long o = ((long)b * 32 + n) * j.Nbig + m0 + m4;
            *(uint2*)(j.Ch + o) = make_uint2(
                ((uint32_t)*(uint16_t*)&h0) | ((uint32_t)*(uint16_t*)&h1 << 16),
                ((uint32_t)*(uint16_t*)&h2) | ((uint32_t)*(uint16_t*)&h3 << 16));
            *(uint2*)(j.Cl + o) = make_uint2(
                ((uint32_t)*(uint16_t*)&l0) | ((uint32_t)*(uint16_t*)&l1 << 16),
                ((uint32_t)*(uint16_t*)&l2) | ((uint32_t)*(uint16_t*)&l3 << 16));
            if (EPI == 1) *(float4*)(j.Cf + o) = v;
        }
    }
    if (EPI == 2) {
        if (tid < 64) {
            float zacc = 0.f;
#pragma unroll
            for (int k = 0; k < KK_; k++)
                zacc += smw[k] * tanhf(Cs[k * CST + tid] + Cs[(32 + k) * CST + tid]);
            j.z[(long)b * j.Nbig + m0 + tid] = zacc;
        }
    }
    if (EPI == 3) {
        if (tid < 64) {
            const float* X = j.Cf + (long)b * 32 * j.Nbig + m0 + tid;
            float zacc = 0.f;
#pragma unroll
            for (int k = 0; k < KK_; k++)
                zacc += smw[k] * tanhf(Cs[k * CST + tid] + X[(long)k * j.Nbig]);
            j.z[(long)b * j.Nbig + m0 + tid] = zacc;
        }
    }
}

// ===================== fused tail kernels ======================================
// one launch: blocks [0,B_) -> zv rows (n=M), [B_,2B_) -> zq rows (n=L)
__global__ void softmax2_kernel(float* __restrict__ zv, float* __restrict__ zq)
{
    const int blk = blockIdx.x;
    const int n = (blk < B_) ? M_ : L_;
    float* row = (blk < B_) ? (zv + (long)blk * M_) : (zq + (long)(blk - B_) * L_);
    __shared__ float red[256];
    const int tid = threadIdx.x;

    float mx = -1e30f;
    for (int i = tid; i < n; i += 256) mx = fmaxf(mx, row[i]);
    red[tid] = mx; __syncthreads();
    for (int s = 128; s > 0; s >>= 1) {
        if (tid < s) red[tid] = fmaxf(red[tid], red[tid + s]);
        __syncthreads();
    }
    mx = red[0]; __syncthreads();

    float sum = 0.f;
    for (int i = tid; i < n; i += 256) {
        float e = expf(row[i] - mx);
        row[i] = e;
        sum += e;
    }
    red[tid] = sum; __syncthreads();
    for (int s = 128; s > 0; s >>= 1) {
        if (tid < s) red[tid] += red[tid + s];
        __syncthreads();
    }
    float inv = 1.f / red[0];
    for (int i = tid; i < n; i += 256) row[i] *= inv;
}

// one launch: blocks [0, 64*B_) -> pool_v ; [64*B_, 64*B_+B_) -> pool_q
__global__ void pool_both(const float* __restrict__ V, const float* __restrict__ Q,
                          const float* __restrict__ av, const float* __restrict__ aq,
                          float* __restrict__ v1, float* __restrict__ q1)
{
    const int blk = blockIdx.x;
    const int tid = threadIdx.x;
    if (blk < 64 * B_) {
        const int b = blk >> 6;
        const int xd = blk & 63;
        const int warp = tid >> 5, lane = tid & 31;
        const int d = xd * 8 + warp;
        const float4* vr = reinterpret_cast<const float4*>(V + ((long)b * D_ + d) * M_);
        const float4* ar = reinterpret_cast<const float4*>(av + (long)b * M_);
        float acc = 0.f;
#pragma unroll
        for (int i = 0; i < M_ / 128; i++) {
            float4 v = vr[i * 32 + lane];
            float4 w = ar[i * 32 + lane];
            acc += v.x * w.x + v.y * w.y + v.z * w.z + v.w * w.w;
        }
#pragma unroll
        for (int o = 16; o > 0; o >>= 1) acc += __shfl_down_sync(0xffffffffu, acc, o);
        if (lane == 0) v1[b * D_ + d] = acc;
    } else {
        const int b = blk - 64 * B_;
        __shared__ float as[L_];
        for (int i = tid; i < L_; i += 256) as[i] = aq[b * L_ + i];
        __syncthreads();
        const float* qb = Q + (long)b * L_ * D_;
#pragma unroll
        for (int r = 0; r < 2; r++) {
            const int d = tid + r * 256;
            float acc = 0.f;
#pragma unroll 8
            for (int l = 0; l < L_; l++) acc += as[l] * qb[(long)l * D_ + d];
            q1[b * D_ + d] = acc;
        }
    }
}

// single launch: writes v region [B,M,D] then q region [B,L,D]
__global__ void bcast_all(float4* __restrict__ out,
                          const float4* __restrict__ v1,
                          const float4* __restrict__ q1)
{
    const long nv4 = (long)B_ * M_ * (D_ / 4);
    const long nq4 = (long)B_ * L_ * (D_ / 4);
    long i = (long)blockIdx.x * blockDim.x + threadIdx.x;
    if (i < nv4) {
        int d4 = (int)(i % (D_ / 4));
        int b = (int)((i / (D_ / 4)) / M_);
        out[i] = __ldg(&v1[(long)b * (D_ / 4) + d4]);
    } else if (i < nv4 + nq4) {
        long k = i - nv4;
        int d4 = (int)(k % (D_ / 4));
        int b = (int)((k / (D_ / 4)) / L_);
        out[i] = __ldg(&q1[(long)b * (D_ / 4) + d4]);
    }
}

// ===================== launch =================================================
extern "C" void kernel_launch(void* const* d_in, const int* in_sizes, int n_in,
                              void* d_out, int out_size)
{
    const float* V   = (const float*)d_in[0];  // [B, D, M]
    const float* Q   = (const float*)d_in[1];  // [B, L, D]
    const float* W_b = (const float*)d_in[2];  // [D, D]
    const float* W_v = (const float*)d_in[3];  // [K, D]
    const float* W_q = (const float*)d_in[4];  // [K, D]
    const float* whv = (const float*)d_in[5];  // [K]
    const float* whq = (const float*)d_in[6];  // [K]
    float* out = (float*)d_out;

    bf16 *pWv_h, *pWv_l, *pWq_h, *pWq_l;
    bf16 *pWqQ_h, *pWqQ_l, *pP_h, *pP_l, *pYv_h, *pYv_l;
    bf16 *pWvV_h, *pWvV_l, *pYq_h, *pYq_l, *pR_h, *pR_l;
    float *pWqQ_f, *p_zv, *p_zq, *p_v1, *p_q1;
    cudaGetSymbolAddress((void**)&pWv_h, g_Wv_hi);  cudaGetSymbolAddress((void**)&pWv_l, g_Wv_lo);
    cudaGetSymbolAddress((void**)&pWq_h, g_Wq_hi);  cudaGetSymbolAddress((void**)&pWq_l, g_Wq_lo);
    cudaGetSymbolAddress((void**)&pWqQ_h, g_WqQ_hi); cudaGetSymbolAddress((void**)&pWqQ_l, g_WqQ_lo);
    cudaGetSymbolAddress((void**)&pWqQ_f, g_WqQ_f);
    cudaGetSymbolAddress((void**)&pP_h, g_P_hi);    cudaGetSymbolAddress((void**)&pP_l, g_P_lo);
    cudaGetSymbolAddress((void**)&pYv_h, g_Yv_hi);  cudaGetSymbolAddress((void**)&pYv_l, g_Yv_lo);
    cudaGetSymbolAddress((void**)&pWvV_h, g_WvV_hi); cudaGetSymbolAddress((void**)&pWvV_l, g_WvV_lo);
    cudaGetSymbolAddress((void**)&pYq_h, g_Yq_hi);  cudaGetSymbolAddress((void**)&pYq_l, g_Yq_lo);
    cudaGetSymbolAddress((void**)&pR_h, g_R_hi);    cudaGetSymbolAddress((void**)&pR_l, g_R_lo);
    cudaGetSymbolAddress((void**)&p_zv, g_zv);      cudaGetSymbolAddress((void**)&p_zq, g_zq);
    cudaGetSymbolAddress((void**)&p_v1, g_v1);      cudaGetSymbolAddress((void**)&p_q1, g_q1);

    const int SM1 = (int)(BS_OFF + 1 * 4 * B_BUF + 128);  // 30848
    const int SM2 = (int)(BS_OFF + 2 * 4 * B_BUF + 128);  // 41088
    cudaFuncSetAttribute(tc_gemm<1, 1, false>, cudaFuncAttributeMaxDynamicSharedMemorySize, SM1);
    cudaFuncSetAttribute(tc_gemm<1, 0, true>,  cudaFuncAttributeMaxDynamicSharedMemorySize, SM1);
    cudaFuncSetAttribute(tc_gemm<2, 2, true>,  cudaFuncAttributeMaxDynamicSharedMemorySize, SM2);
    cudaFuncSetAttribute(tc_gemm<1, 0, false>, cudaFuncAttributeMaxDynamicSharedMemorySize, SM1);
    cudaFuncSetAttribute(tc_gemm<1, 3, false>, cudaFuncAttributeMaxDynamicSharedMemorySize, SM1);

    conv_pad<<<(32 * D_ + 255) / 256, 256>>>(W_v, pWv_h, pWv_l, W_q, pWq_h, pWq_l);

    GJob j;
    // K1: WqQ[k,l] = sum_d Wq[k,d] Q[l,d] : A=Q AN [L][D]; hi/lo + fp32 out
    j = { Q, D_, (long)L_ * D_, pWq_h, pWq_l, nullptr, nullptr,
          pWqQ_h, pWqQ_l, pWqQ_f, nullptr, nullptr, L_, D_, 0, 0 };
    tc_gemm<1, 1, false><<<dim3(L_ / 64, B_), 128, SM1>>>(j);

    // K2: P[k,e] = sum_l WqQ[k,l] Q[l,e] : A=Q TRA (lda=D), Kd=L
    j = { Q, D_, (long)L_ * D_, pWqQ_h, pWqQ_l, nullptr, nullptr,
          pP_h, pP_l, nullptr, nullptr, nullptr, D_, L_, (long)32 * L_, 0 };
    tc_gemm<1, 0, true><<<dim3(D_ / 64, B_), 128, SM1>>>(j);

    // K3: Yv[k,e] = sum_d P[k,d] Wb[d,e] : A=Wb TRA (no batch)
    j = { W_b, D_, 0, pP_h, pP_l, nullptr, nullptr,
          pYv_h, pYv_l, nullptr, nullptr, nullptr, D_, D_, (long)32 * D_, 0 };
    tc_gemm<1, 0, true><<<dim3(D_ / 64, B_), 128, SM1>>>(j);

    // K4+K5+logits_v: A=V TRA (lda=M); B0=Wv -> WvV; B1=Yv -> Tv (fused logits)
    j = { V, M_, (long)D_ * M_, pWv_h, pWv_l, pYv_h, pYv_l,
          pWvV_h, pWvV_l, nullptr, whv, p_zv, M_, D_, 0, (long)32 * D_ };
    tc_gemm<2, 2, true><<<dim3(M_ / 64, B_), 128, SM2>>>(j);

    // K6: Yq[k,e] = sum_m WvV[k,m] V[e,m] : A=V AN [D][M], Kd=M
    j = { V, M_, (long)D_ * M_, pWvV_h, pWvV_l, nullptr, nullptr,
          pYq_h, pYq_l, nullptr, nullptr, nullptr, D_, M_, (long)32 * M_, 0 };
    tc_gemm<1, 0, false><<<dim3(D_ / 64, B_), 128, SM1>>>(j);

    // K7: R[k,d] = sum_e Yq[k,e] Wb[d,e] : A=Wb AN (no batch)
    j = { W_b, D_, 0, pYq_h, pYq_l, nullptr, nullptr,
          pR_h, pR_l, nullptr, nullptr, nullptr, D_, D_, (long)32 * D_, 0 };
    tc_gemm<1, 0, false><<<dim3(D_ / 64, B_), 128, SM1>>>(j);

    // K8+logits_q: Tq[k,l] = sum_d R[k,d] Q[l,d] : A=Q AN; X=WqQ_f
    j = { Q, D_, (long)L_ * D_, pR_h, pR_l, nullptr, nullptr,
          nullptr, nullptr, pWqQ_f, whq, p_zq, L_, D_, (long)32 * D_, 0 };
    tc_gemm<1, 3, false><<<dim3(L_ / 64, B_), 128, SM1>>>(j);

    // fused softmax (zv + zq in one launch)
    softmax2_kernel<<<2 * B_, 256>>>(p_zv, p_zq);

    // fused pooling (pool_v + pool_q in one launch)
    pool_both<<<64 * B_ + B_, 256>>>(V, Q, p_zv, p_zq, p_v1, p_q1);

    // broadcast both outputs in one launch
    {
        long n4 = (long)B_ * (M_ + L_) * (D_ / 4);
        bcast_all<<<(unsigned)((n4 + 255) / 256), 256>>>(
            (float4*)out, (const float4*)p_v1, (const float4*)p_q1);
    }
}

// round 14
// speedup vs baseline: 1.1864x; 1.1432x over previous
#include <cuda_runtime.h>
#include <cuda_bf16.h>
#include <math.h>
#include <stdint.h>

// Problem dims (fixed)
#define B_ 64
#define D_ 512
#define M_ 1024
#define L_ 256
#define KK_ 30

typedef __nv_bfloat16 bf16;

// ===================== device scratch =========================================
__device__ bf16 g_Wv_hi[32 * D_];
__device__ bf16 g_Wv_lo[32 * D_];
__device__ bf16 g_Wq_hi[32 * D_];
__device__ bf16 g_Wq_lo[32 * D_];
__device__ bf16 g_WqQ_hi[(long)B_ * 32 * L_];
__device__ bf16 g_WqQ_lo[(long)B_ * 32 * L_];
__device__ float g_WqQ_f[(long)B_ * 32 * L_];
__device__ bf16 g_P_hi[(long)B_ * 32 * D_];
__device__ bf16 g_P_lo[(long)B_ * 32 * D_];
__device__ bf16 g_Yv_hi[(long)B_ * 32 * D_];
__device__ bf16 g_Yv_lo[(long)B_ * 32 * D_];
__device__ bf16 g_WvV_hi[(long)B_ * 32 * M_];
__device__ bf16 g_WvV_lo[(long)B_ * 32 * M_];
__device__ bf16 g_Yq_hi[(long)B_ * 32 * D_];
__device__ bf16 g_Yq_lo[(long)B_ * 32 * D_];
__device__ bf16 g_R_hi[(long)B_ * 32 * D_];
__device__ bf16 g_R_lo[(long)B_ * 32 * D_];
__device__ float g_zv[B_ * M_];
__device__ float g_zq[B_ * L_];
__device__ float g_v1[B_ * D_];
__device__ float g_q1[B_ * D_];

// ===================== helpers ================================================
__device__ __forceinline__ uint32_t s2u(const void* p) {
    return (uint32_t)__cvta_generic_to_shared(p);
}
__device__ __forceinline__ void cp16(uint32_t dst, const void* src) {
    asm volatile("cp.async.cg.shared.global [%0], [%1], 16;" :: "r"(dst), "l"(src));
}
__device__ __forceinline__ void cp_commit() { asm volatile("cp.async.commit_group;"); }
__device__ __forceinline__ void cp_wait0()  { asm volatile("cp.async.wait_group 0;"); }

__device__ __forceinline__ void ldsm4(uint32_t* r, uint32_t addr) {
    asm volatile("ldmatrix.sync.aligned.m8n8.x4.shared.b16 {%0,%1,%2,%3}, [%4];"
                 : "=r"(r[0]), "=r"(r[1]), "=r"(r[2]), "=r"(r[3]) : "r"(addr));
}
__device__ __forceinline__ void ldsm4t(uint32_t* r, uint32_t addr) {
    asm volatile("ldmatrix.sync.aligned.m8n8.x4.trans.shared.b16 {%0,%1,%2,%3}, [%4];"
                 : "=r"(r[0]), "=r"(r[1]), "=r"(r[2]), "=r"(r[3]) : "r"(addr));
}
__device__ __forceinline__ void mma_bf(float* d, const uint32_t* a, const uint32_t* b) {
    asm volatile(
        "mma.sync.aligned.m16n8k16.row.col.f32.bf16.bf16.f32 "
        "{%0,%1,%2,%3}, {%4,%5,%6,%7}, {%8,%9}, {%0,%1,%2,%3};"
        : "+f"(d[0]), "+f"(d[1]), "+f"(d[2]), "+f"(d[3])
        : "r"(a[0]), "r"(a[1]), "r"(a[2]), "r"(a[3]), "r"(b[0]), "r"(b[1]));
}
__device__ __forceinline__ void split_bf(float x, bf16& h, bf16& l) {
    h = __float2bfloat16(x);
    l = __float2bfloat16(x - __bfloat162float(h));
}

// smem layout constants (bytes) -- 64-row m-tiles, 128-thread CTAs
#define A_BUF 5120u      // AN: 64 rows x 80B ; TRA: 32 rows x 144B (4608 <= slot)
#define B_BUF 2560u      // 32 x 40 bf16
#define BS_OFF 20480u    // after 4 A slots
#define CST 132          // epilogue staging n-stride (floats)

// ===================== weight pad conversion ==================================
__global__ void conv_pad(const float* __restrict__ Wv, bf16* __restrict__ Vh, bf16* __restrict__ Vl,
                         const float* __restrict__ Wq, bf16* __restrict__ Qh, bf16* __restrict__ Ql)
{
    int idx = blockIdx.x * blockDim.x + threadIdx.x;
    if (idx >= 32 * D_) return;
    int k = idx / D_, d = idx % D_;
    float a = (k < KK_) ? Wv[k * D_ + d] : 0.f;
    float b = (k < KK_) ? Wq[k * D_ + d] : 0.f;
    bf16 h, l;
    split_bf(a, h, l); Vh[idx] = h; Vl[idx] = l;
    split_bf(b, h, l); Qh[idx] = h; Ql[idx] = l;
}

// ===================== HMMA GEMM (R10 pipeline, 64-row tiles) ==================
// Ct[64-row m-tile of Nbig][32] = A(fp32, converted on the fly) x S[32,Kd]^T
struct GJob {
    const float* A;                      // fp32 big operand
    int lda; long sA;
    const bf16 *B0h, *B0l, *B1h, *B1l;   // small operands [32][Kd] bf16
    bf16 *Ch, *Cl;                       // out [b][32][Nbig]
    float* Cf;                           // EPI1: fp32 out; EPI3: fp32 X in
    const float* w;                      // logits weights (EPI 2/3)
    float* z;                            // logits out [b][Nbig]
    int Nbig, Kd;
    long sB0, sB1;
};

// EPI: 0 = hi/lo out; 1 = hi/lo + fp32 out; 2 = (NB=2) hi/lo of acc0 + fused
//      logits(acc0+acc1); 3 = logits(acc0 + fp32 X), no C out
template<int NB, int EPI, bool TRA>
__global__ void __launch_bounds__(128) tc_gemm(GJob j)
{
    extern __shared__ char smem[];
    const uint32_t sb = s2u(smem);
    float* smw = (float*)(smem + BS_OFF + NB * 4 * B_BUF);

    const int tid = threadIdx.x;
    const int w = tid >> 5, lane = tid & 31;
    const int b = blockIdx.y;
    const int m0 = blockIdx.x * 64;

    const float* Ab = j.A + (long)b * j.sA;
    const bf16* Bb[2][2];
    Bb[0][0] = j.B0h + (long)b * j.sB0;
    Bb[0][1] = j.B0l + (long)b * j.sB0;
    if (NB == 2) {
        Bb[1][0] = j.B1h + (long)b * j.sB1;
        Bb[1][1] = j.B1l + (long)b * j.sB1;
    }

    if (EPI >= 2 && tid < KK_) smw[tid] = j.w[tid];

    // A gmem addressing (16 floats per thread per 32-k tile)
    const float* aptr = TRA
        ? (Ab + (long)(tid >> 2) * j.lda + m0 + (tid & 3) * 16)
        : (Ab + (long)(m0 + (tid >> 1)) * j.lda + (tid & 1) * 16);
    const uint32_t aSts = TRA ? (uint32_t)((tid >> 2) * 144 + (tid & 3) * 32)
                              : (uint32_t)((tid >> 1) * 80 + (tid & 1) * 32);

    // B staging indices: 32 rows x 4 cols of 16B, both hl per thread
    const int br = tid >> 2, bc = tid & 3;

    const int T = j.Kd / 32;
    float4 fr[4];

    auto loadA = [&](int t) {
        const float* p = TRA ? (aptr + (long)t * 32 * j.lda) : (aptr + t * 32);
        fr[0] = *(const float4*)p;
        fr[1] = *(const float4*)(p + 4);
        fr[2] = *(const float4*)(p + 8);
        fr[3] = *(const float4*)(p + 12);
    };
    auto stsA = [&](int s) {
        uint32_t hp[8], lp[8];
        const float* f = (const float*)fr;
#pragma unroll
        for (int i = 0; i < 8; i++) {
            bf16 h0, l0, h1, l1;
            split_bf(f[2 * i], h0, l0);
            split_bf(f[2 * i + 1], h1, l1);
            hp[i] = (uint32_t)*(uint16_t*)&h0 | ((uint32_t)*(uint16_t*)&h1 << 16);
            lp[i] = (uint32_t)*(uint16_t*)&l0 | ((uint32_t)*(uint16_t*)&l1 << 16);
        }
        char* d0 = smem + (s * 2 + 0) * A_BUF + aSts;
        char* d1 = smem + (s * 2 + 1) * A_BUF + aSts;
        *(uint4*)d0        = make_uint4(hp[0], hp[1], hp[2], hp[3]);
        *(uint4*)(d0 + 16) = make_uint4(hp[4], hp[5], hp[6], hp[7]);
        *(uint4*)d1        = make_uint4(lp[0], lp[1], lp[2], lp[3]);
        *(uint4*)(d1 + 16) = make_uint4(lp[4], lp[5], lp[6], lp[7]);
    };
    auto stageB = [&](int t) {
        const int s = t & 1;
#pragma unroll
        for (int nb = 0; nb < NB; nb++)
#pragma unroll
        for (int hl = 0; hl < 2; hl++) {
            uint32_t dst = sb + BS_OFF + (uint32_t)(((s * NB + nb) * 2 + hl) * B_BUF)
                         + br * 80 + bc * 16;
            cp16(dst, Bb[nb][hl] + (long)br * j.Kd + t * 32 + bc * 8);
        }
        cp_commit();
    };

    // ldmatrix lane addressing
    const uint32_t aLane = TRA
        ? (uint32_t)((((lane & 7) + 8 * (lane >> 4)) * 144) + (w * 16 + ((lane >> 3) & 1) * 8) * 2)
        : (uint32_t)((w * 16 + (lane & 15)) * 80 + (lane >> 4) * 16);
    const uint32_t aKs = TRA ? 2304u : 32u;
    const uint32_t bLaneRow = (uint32_t)((((lane >> 4) & 1) * 8 + (lane & 7)) * 80
                                         + ((lane >> 3) & 1) * 16);

    float acc[NB][4][4];
#pragma unroll
    for (int nb = 0; nb < NB; nb++)
#pragma unroll
        for (int nt = 0; nt < 4; nt++)
#pragma unroll
            for (int r = 0; r < 4; r++) acc[nb][nt][r] = 0.f;

    stageB(0);
    loadA(0);

    for (int t = 0; t < T; t++) {
        const int s = t & 1;
        cp_wait0();
        __syncthreads();

        stsA(s);
        if (t + 1 < T) { stageB(t + 1); loadA(t + 1); }
        __syncthreads();

        const uint32_t aH = sb + (uint32_t)((s * 2 + 0) * A_BUF) + aLane;
        const uint32_t aL = aH + A_BUF;

#pragma unroll
        for (int ks = 0; ks < 2; ks++) {
            uint32_t ah[4], al[4];
            if (TRA) { ldsm4t(ah, aH + ks * aKs); ldsm4t(al, aL + ks * aKs); }
            else     { ldsm4 (ah, aH + ks * aKs); ldsm4 (al, aL + ks * aKs); }
#pragma unroll
            for (int nb = 0; nb < NB; nb++) {
#pragma unroll
                for (int p = 0; p < 2; p++) {
                    uint32_t bbase = sb + BS_OFF + (uint32_t)(((s * NB + nb) * 2 + 0) * B_BUF)
                        + (uint32_t)(p * 16 * 80) + bLaneRow + ks * 32;
                    uint32_t bh[4], bl[4];
                    ldsm4(bh, bbase);
                    ldsm4(bl, bbase + B_BUF);
                    mma_bf(acc[nb][2 * p],     ah, &bh[0]);
                    mma_bf(acc[nb][2 * p],     ah, &bl[0]);
                    mma_bf(acc[nb][2 * p],     al, &bh[0]);
                    mma_bf(acc[nb][2 * p + 1], ah, &bh[2]);
                    mma_bf(acc[nb][2 * p + 1], ah, &bl[2]);
                    mma_bf(acc[nb][2 * p + 1], al, &bh[2]);
                }
            }
        }
    }

    // ---------------- epilogue: stage accs in smem (reuses A region) ---------
    __syncthreads();
    float* Cs = (float*)smem;
    {
        const int g = lane >> 2, cc = lane & 3;
        const int m_l = w * 16 + g;          // 0..63
#pragma unroll
        for (int nb = 0; nb < NB; nb++) {
            float* C_ = Cs + nb * 32 * CST;
#pragma unroll
            for (int nt = 0; nt < 4; nt++) {
                int n0 = nt * 8 + cc * 2;
                C_[(n0 + 0) * CST + m_l]     = acc[nb][nt][0];
                C_[(n0 + 1) * CST + m_l]     = acc[nb][nt][1];
                C_[(n0 + 0) * CST + m_l + 8] = acc[nb][nt][2];
                C_[(n0 + 1) * CST + m_l + 8] = acc[nb][nt][3];
            }
        }
    }
    __syncthreads();

    if (EPI != 3) {
        // write acc0 tile: 32 n x 64 m = 512 float4, 128 threads x 4 iters
#pragma unroll
        for (int it = 0; it < 4; it++) {
            int q = tid + it * 128;
            int n = q >> 4, m4 = (q & 15) * 4;
            float4 v = *(float4*)&Cs[n * CST + m4];
            bf16 h0, l0, h1, l1, h2, l2, h3, l3;
            split_bf(v.x, h0, l0); split_bf(v.y, h1, l1);
            split_bf(v.z, h2, l2); split_bf(v.w, h3, l3);
            long o = ((long)b * 32 + n) * j.Nbig + m0 + m4;
            *(uint2*)(j.Ch + o) = make_uint2(
                ((uint32_t)*(uint16_t*)&h0) | ((uint32_t)*(uint16_t*)&h1 << 16),
                ((uint32_t)*(uint16_t*)&h2) | ((uint32_t)*(uint16_t*)&h3 << 16));
            *(uint2*)(j.Cl + o) = make_uint2(
                ((uint32_t)*(uint16_t*)&l0) | ((uint32_t)*(uint16_t*)&l1 << 16),
                ((uint32_t)*(uint16_t*)&l2) | ((uint32_t)*(uint16_t*)&l3 << 16));
            if (EPI == 1) *(float4*)(j.Cf + o) = v;
        }
    }
    if (EPI == 2) {
        if (tid < 64) {
            float zacc = 0.f;
#pragma unroll
            for (int k = 0; k < KK_; k++)
                zacc += smw[k] * tanhf(Cs[k * CST + tid] + Cs[(32 + k) * CST + tid]);
            j.z[(long)b * j.Nbig + m0 + tid] = zacc;
        }
    }
    if (EPI == 3) {
        if (tid < 64) {
            const float* X = j.Cf + (long)b * 32 * j.Nbig + m0 + tid;
            float zacc = 0.f;
#pragma unroll
            for (int k = 0; k < KK_; k++)
                zacc += smw[k] * tanhf(Cs[k * CST + tid] + X[(long)k * j.Nbig]);
            j.z[(long)b * j.Nbig + m0 + tid] = zacc;
        }
    }
}

// ===================== tail kernels (R10 originals) ============================
__global__ void softmax_kernel(float* __restrict__ z, int n)
{
    const int b = blockIdx.x;
    float* row = z + (long)b * n;
    __shared__ float red[256];
    const int tid = threadIdx.x;

    float mx = -1e30f;
    for (int i = tid; i < n; i += 256) mx = fmaxf(mx, row[i]);
    red[tid] = mx; __syncthreads();
    for (int s = 128; s > 0; s >>= 1) {
        if (tid < s) red[tid] = fmaxf(red[tid], red[tid + s]);
        __syncthreads();
    }
    mx = red[0]; __syncthreads();

    float sum = 0.f;
    for (int i = tid; i < n; i += 256) {
        float e = expf(row[i] - mx);
        row[i] = e;
        sum += e;
    }
    red[tid] = sum; __syncthreads();
    for (int s = 128; s > 0; s >>= 1) {
        if (tid < s) red[tid] += red[tid + s];
        __syncthreads();
    }
    float inv = 1.f / red[0];
    for (int i = tid; i < n; i += 256) row[i] *= inv;
}

__global__ void pool_v_kernel(const float* __restrict__ V,
                              const float* __restrict__ a,
                              float* __restrict__ v1)
{
    const int b = blockIdx.y;
    const int warp = threadIdx.x >> 5;
    const int lane = threadIdx.x & 31;
    const int d = blockIdx.x * 8 + warp;
    const float4* vr = reinterpret_cast<const float4*>(V + ((long)b * D_ + d) * M_);
    const float4* ar = reinterpret_cast<const float4*>(a + (long)b * M_);
    float acc = 0.f;
#pragma unroll
    for (int i = 0; i < M_ / 128; i++) {
        float4 v = vr[i * 32 + lane];
        float4 w = ar[i * 32 + lane];
        acc += v.x * w.x + v.y * w.y + v.z * w.z + v.w * w.w;
    }
#pragma unroll
    for (int o = 16; o > 0; o >>= 1) acc += __shfl_down_sync(0xffffffffu, acc, o);
    if (lane == 0) v1[b * D_ + d] = acc;
}

__global__ void pool_q_kernel(const float* __restrict__ Q,
                              const float* __restrict__ a,
                              float* __restrict__ q1)
{
    const int b = blockIdx.x;
    __shared__ float as[L_];
    for (int i = threadIdx.x; i < L_; i += blockDim.x) as[i] = a[b * L_ + i];
    __syncthreads();
    const int d = threadIdx.x;
    const float* qb = Q + (long)b * L_ * D_;
    float acc = 0.f;
#pragma unroll 8
    for (int l = 0; l < L_; l++) acc += as[l] * qb[(long)l * D_ + d];
    q1[b * D_ + d] = acc;
}

__global__ void bcast_kernel(float4* __restrict__ out,
                             const float4* __restrict__ src,
                             int rows)
{
    const long total4 = (long)B_ * rows * (D_ / 4);
    long i = (long)blockIdx.x * blockDim.x + threadIdx.x;
    if (i >= total4) return;
    int d4 = (int)(i % (D_ / 4));
    long br = i / (D_ / 4);
    int b = (int)(br / rows);
    out[i] = __ldg(&src[(long)b * (D_ / 4) + d4]);
}

// ===================== launch =================================================
extern "C" void kernel_launch(void* const* d_in, const int* in_sizes, int n_in,
                              void* d_out, int out_size)
{
    const float* V   = (const float*)d_in[0];  // [B, D, M]
    const float* Q   = (const float*)d_in[1];  // [B, L, D]
    const float* W_b = (const float*)d_in[2];  // [D, D]
    const float* W_v = (const float*)d_in[3];  // [K, D]
    const float* W_q = (const float*)d_in[4];  // [K, D]
    const float* whv = (const float*)d_in[5];  // [K]
    const float* whq = (const float*)d_in[6];  // [K]
    float* out = (float*)d_out;

    bf16 *pWv_h, *pWv_l, *pWq_h, *pWq_l;
    bf16 *pWqQ_h, *pWqQ_l, *pP_h, *pP_l, *pYv_h, *pYv_l;
    bf16 *pWvV_h, *pWvV_l, *pYq_h, *pYq_l, *pR_h, *pR_l;
    float *pWqQ_f, *p_zv, *p_zq, *p_v1, *p_q1;
    cudaGetSymbolAddress((void**)&pWv_h, g_Wv_hi);  cudaGetSymbolAddress((void**)&pWv_l, g_Wv_lo);
    cudaGetSymbolAddress((void**)&pWq_h, g_Wq_hi);  cudaGetSymbolAddress((void**)&pWq_l, g_Wq_lo);
    cudaGetSymbolAddress((void**)&pWqQ_h, g_WqQ_hi); cudaGetSymbolAddress((void**)&pWqQ_l, g_WqQ_lo);
    cudaGetSymbolAddress((void**)&pWqQ_f, g_WqQ_f);
    cudaGetSymbolAddress((void**)&pP_h, g_P_hi);    cudaGetSymbolAddress((void**)&pP_l, g_P_lo);
    cudaGetSymbolAddress((void**)&pYv_h, g_Yv_hi);  cudaGetSymbolAddress((void**)&pYv_l, g_Yv_lo);
    cudaGetSymbolAddress((void**)&pWvV_h, g_WvV_hi); cudaGetSymbolAddress((void**)&pWvV_l, g_WvV_lo);
    cudaGetSymbolAddress((void**)&pYq_h, g_Yq_hi);  cudaGetSymbolAddress((void**)&pYq_l, g_Yq_lo);
    cudaGetSymbolAddress((void**)&pR_h, g_R_hi);    cudaGetSymbolAddress((void**)&pR_l, g_R_lo);
    cudaGetSymbolAddress((void**)&p_zv, g_zv);      cudaGetSymbolAddress((void**)&p_zq, g_zq);
    cudaGetSymbolAddress((void**)&p_v1, g_v1);      cudaGetSymbolAddress((void**)&p_q1, g_q1);

    const int SM1 = (int)(BS_OFF + 1 * 4 * B_BUF + 128);  // 30848
    const int SM2 = (int)(BS_OFF + 2 * 4 * B_BUF + 128);  // 41088
    cudaFuncSetAttribute(tc_gemm<1, 1, false>, cudaFuncAttributeMaxDynamicSharedMemorySize, SM1);
    cudaFuncSetAttribute(tc_gemm<1, 0, true>,  cudaFuncAttributeMaxDynamicSharedMemorySize, SM1);
    cudaFuncSetAttribute(tc_gemm<2, 2, true>,  cudaFuncAttributeMaxDynamicSharedMemorySize, SM2);
    cudaFuncSetAttribute(tc_gemm<1, 0, false>, cudaFuncAttributeMaxDynamicSharedMemorySize, SM1);
    cudaFuncSetAttribute(tc_gemm<1, 3, false>, cudaFuncAttributeMaxDynamicSharedMemorySize, SM1);

    // fork/join machinery (created+destroyed per call; host objects only)
    cudaStream_t s2;
    cudaEvent_t evFork, evJoin;
    cudaStreamCreateWithFlags(&s2, cudaStreamNonBlocking);
    cudaEventCreateWithFlags(&evFork, cudaEventDisableTiming);
    cudaEventCreateWithFlags(&evJoin, cudaEventDisableTiming);

    conv_pad<<<(32 * D_ + 255) / 256, 256>>>(W_v, pWv_h, pWv_l, W_q, pWq_h, pWq_l);

    GJob j;
    // K1: WqQ[k,l] = sum_d Wq[k,d] Q[l,d] : A=Q AN [L][D]; hi/lo + fp32 out
    j = { Q, D_, (long)L_ * D_, pWq_h, pWq_l, nullptr, nullptr,
          pWqQ_h, pWqQ_l, pWqQ_f, nullptr, nullptr, L_, D_, 0, 0 };
    tc_gemm<1, 1, false><<<dim3(L_ / 64, B_), 128, SM1>>>(j);

    // K2: P[k,e] = sum_l WqQ[k,l] Q[l,e] : A=Q TRA (lda=D), Kd=L
    j = { Q, D_, (long)L_ * D_, pWqQ_h, pWqQ_l, nullptr, nullptr,
          pP_h, pP_l, nullptr, nullptr, nullptr, D_, L_, (long)32 * L_, 0 };
    tc_gemm<1, 0, true><<<dim3(D_ / 64, B_), 128, SM1>>>(j);

    // K3: Yv[k,e] = sum_d P[k,d] Wb[d,e] : A=Wb TRA (no batch)
    j = { W_b, D_, 0, pP_h, pP_l, nullptr, nullptr,
          pYv_h, pYv_l, nullptr, nullptr, nullptr, D_, D_, (long)32 * D_, 0 };
    tc_gemm<1, 0, true><<<dim3(D_ / 64, B_), 128, SM1>>>(j);

    // K4+K5+logits_v: A=V TRA (lda=M); B0=Wv -> WvV; B1=Yv -> Tv (fused logits)
    j = { V, M_, (long)D_ * M_, pWv_h, pWv_l, pYv_h, pYv_l,
          pWvV_h, pWvV_l, nullptr, whv, p_zv, M_, D_, 0, (long)32 * D_ };
    tc_gemm<2, 2, true><<<dim3(M_ / 64, B_), 128, SM2>>>(j);

    // ---- fork: v-tail on s2 (depends only on z_v), K6..K8+q-tail on default
    cudaEventRecord(evFork, 0);
    cudaStreamWaitEvent(s2, evFork, 0);

    // v-tail on s2
    softmax_kernel<<<B_, 256, 0, s2>>>(p_zv, M_);
    {
        dim3 grid(D_ / 8, B_);
        pool_v_kernel<<<grid, 256, 0, s2>>>(V, p_zv, p_v1);
    }
    {
        long n4v = (long)B_ * M_ * (D_ / 4);
        bcast_kernel<<<(unsigned)((n4v + 255) / 256), 256, 0, s2>>>(
            (float4*)out, (const float4*)p_v1, M_);
    }

    // K6: Yq[k,e] = sum_m WvV[k,m] V[e,m] : A=V AN [D][M], Kd=M
    j = { V, M_, (long)D_ * M_, pWvV_h, pWvV_l, nullptr, nullptr,
          pYq_h, pYq_l, nullptr, nullptr, nullptr, D_, M_, (long)32 * M_, 0 };
    tc_gemm<1, 0, false><<<dim3(D_ / 64, B_), 128, SM1>>>(j);

    // K7: R[k,d] = sum_e Yq[k,e] Wb[d,e] : A=Wb AN (no batch)
    j = { W_b, D_, 0, pYq_h, pYq_l, nullptr, nullptr,
          pR_h, pR_l, nullptr, nullptr, nullptr, D_, D_, (long)32 * D_, 0 };
    tc_gemm<1, 0, false><<<dim3(D_ / 64, B_), 128, SM1>>>(j);

    // K8+logits_q: Tq[k,l] = sum_d R[k,d] Q[l,d] : A=Q AN; X=WqQ_f
    j = { Q, D_, (long)L_ * D_, pR_h, pR_l, nullptr, nullptr,
          nullptr, nullptr, pWqQ_f, whq, p_zq, L_, D_, (long)32 * D_, 0 };
    tc_gemm<1, 3, false><<<dim3(L_ / 64, B_), 128, SM1>>>(j);

    // q-tail on default stream
    softmax_kernel<<<B_, 256>>>(p_zq, L_);
    pool_q_kernel<<<B_, 512>>>(Q, p_zq, p_q1);
    {
        long n4q = (long)B_ * L_ * (D_ / 4);
        float* out_q = out + (long)B_ * M_ * D_;
        bcast_kernel<<<(unsigned)((n4q + 255) / 256), 256>>>(
            (float4*)out_q, (const float4*)p_q1, L_);
    }

    // ---- join: default stream waits for v-tail
    cudaEventRecord(evJoin, s2);
    cudaStreamWaitEvent(0, evJoin, 0);

    cudaEventDestroy(evFork);
    cudaEventDestroy(evJoin);
    cudaStreamDestroy(s2);
}

// round 15
// speedup vs baseline: 1.2090x; 1.0190x over previous
#include <cuda_runtime.h>
#include <cuda_bf16.h>
#include <math.h>
#include <stdint.h>

// Problem dims (fixed)
#define B_ 64
#define D_ 512
#define M_ 1024
#define L_ 256
#define KK_ 30

typedef __nv_bfloat16 bf16;

// ===================== device scratch =========================================
__device__ bf16 g_Wv_hi[32 * D_];
__device__ bf16 g_Wv_lo[32 * D_];
__device__ bf16 g_Wq_hi[32 * D_];
__device__ bf16 g_Wq_lo[32 * D_];
__device__ bf16 g_WqQ_hi[(long)B_ * 32 * L_];
__device__ bf16 g_WqQ_lo[(long)B_ * 32 * L_];
__device__ float g_WqQ_f[(long)B_ * 32 * L_];
__device__ bf16 g_P_hi[(long)B_ * 32 * D_];
__device__ bf16 g_P_lo[(long)B_ * 32 * D_];
__device__ bf16 g_Yv_hi[(long)B_ * 32 * D_];
__device__ bf16 g_Yv_lo[(long)B_ * 32 * D_];
__device__ bf16 g_WvV_hi[(long)B_ * 32 * M_];
__device__ bf16 g_WvV_lo[(long)B_ * 32 * M_];
__device__ float g_WvV_f[(long)B_ * 32 * M_];
__device__ bf16 g_Yq_hi[(long)B_ * 32 * D_];
__device__ bf16 g_Yq_lo[(long)B_ * 32 * D_];
__device__ bf16 g_R_hi[(long)B_ * 32 * D_];
__device__ bf16 g_R_lo[(long)B_ * 32 * D_];
__device__ float g_zv[B_ * M_];
__device__ float g_zq[B_ * L_];
__device__ float g_v1[B_ * D_];
__device__ float g_q1[B_ * D_];

// ===================== helpers ================================================
__device__ __forceinline__ uint32_t s2u(const void* p) {
    return (uint32_t)__cvta_generic_to_shared(p);
}
__device__ __forceinline__ void cp16(uint32_t dst, const void* src) {
    asm volatile("cp.async.cg.shared.global [%0], [%1], 16;" :: "r"(dst), "l"(src));
}
__device__ __forceinline__ void cp_commit() { asm volatile("cp.async.commit_group;"); }
__device__ __forceinline__ void cp_wait0()  { asm volatile("cp.async.wait_group 0;"); }

__device__ __forceinline__ void ldsm4(uint32_t* r, uint32_t addr) {
    asm volatile("ldmatrix.sync.aligned.m8n8.x4.shared.b16 {%0,%1,%2,%3}, [%4];"
                 : "=r"(r[0]), "=r"(r[1]), "=r"(r[2]), "=r"(r[3]) : "r"(addr));
}
__device__ __forceinline__ void ldsm4t(uint32_t* r, uint32_t addr) {
    asm volatile("ldmatrix.sync.aligned.m8n8.x4.trans.shared.b16 {%0,%1,%2,%3}, [%4];"
                 : "=r"(r[0]), "=r"(r[1]), "=r"(r[2]), "=r"(r[3]) : "r"(addr));
}
__device__ __forceinline__ void mma_bf(float* d, const uint32_t* a, const uint32_t* b) {
    asm volatile(
        "mma.sync.aligned.m16n8k16.row.col.f32.bf16.bf16.f32 "
        "{%0,%1,%2,%3}, {%4,%5,%6,%7}, {%8,%9}, {%0,%1,%2,%3};"
        : "+f"(d[0]), "+f"(d[1]), "+f"(d[2]), "+f"(d[3])
        : "r"(a[0]), "r"(a[1]), "r"(a[2]), "r"(a[3]), "r"(b[0]), "r"(b[1]));
}
__device__ __forceinline__ void split_bf(float x, bf16& h, bf16& l) {
    h = __float2bfloat16(x);
    l = __float2bfloat16(x - __bfloat162float(h));
}

// smem layout constants (bytes) -- 64-row m-tiles, 128-thread CTAs
#define A_BUF 5120u      // AN: 64 rows x 80B ; TRA: 32 rows x 144B (4608 <= slot)
#define B_BUF 2560u      // 32 x 40 bf16
#define BS_OFF 20480u    // after 4 A slots
#define CST 132          // epilogue staging n-stride (floats)

// ===================== weight pad conversion ==================================
__global__ void conv_pad(const float* __restrict__ Wv, bf16* __restrict__ Vh, bf16* __restrict__ Vl,
                         const float* __restrict__ Wq, bf16* __restrict__ Qh, bf16* __restrict__ Ql)
{
    int idx = blockIdx.x * blockDim.x + threadIdx.x;
    if (idx >= 32 * D_) return;
    int k = idx / D_, d = idx % D_;
    float a = (k < KK_) ? Wv[k * D_ + d] : 0.f;
    float b = (k < KK_) ? Wq[k * D_ + d] : 0.f;
    bf16 h, l;
    split_bf(a, h, l); Vh[idx] = h; Vl[idx] = l;
    split_bf(b, h, l); Qh[idx] = h; Ql[idx] = l;
}

// ===================== HMMA GEMM (R10 pipeline, 64-row tiles) ==================
// Ct[64-row m-tile of Nbig][32] = A(fp32, converted on the fly) x S[32,Kd]^T
struct GJob {
    const float* A;                      // fp32 big operand
    int lda; long sA;
    const bf16 *B0h, *B0l, *B1h, *B1l;   // small operands [32][Kd] bf16
    bf16 *Ch, *Cl;                       // out [b][32][Nbig]
    float* Cf;                           // EPI1: fp32 out; EPI3: fp32 X in
    const float* w;                      // logits weights (EPI 2/3)
    float* z;                            // logits out [b][Nbig]
    int Nbig, Kd;
    long sB0, sB1;
};

// EPI: 0 = hi/lo out; 1 = hi/lo + fp32 out; 2 = (NB=2) hi/lo of acc0 + fused
//      logits(acc0+acc1); 3 = logits(acc0 + fp32 X), no C out
template<int NB, int EPI, bool TRA>
__global__ void __launch_bounds__(128) tc_gemm(GJob j)
{
    extern __shared__ char smem[];
    const uint32_t sb = s2u(smem);
    float* smw = (float*)(smem + BS_OFF + NB * 4 * B_BUF);

    const int tid = threadIdx.x;
    const int w = tid >> 5, lane = tid & 31;
    const int b = blockIdx.y;
    const int m0 = blockIdx.x * 64;

    const float* Ab = j.A + (long)b * j.sA;
    const bf16* Bb[2][2];
    Bb[0][0] = j.B0h + (long)b * j.sB0;
    Bb[0][1] = j.B0l + (long)b * j.sB0;
    if (NB == 2) {
        Bb[1][0] = j.B1h + (long)b * j.sB1;
        Bb[1][1] = j.B1l + (long)b * j.sB1;
    }

    if (EPI >= 2 && tid < KK_) smw[tid] = j.w[tid];

    // A gmem addressing (16 floats per thread per 32-k tile)
    const float* aptr = TRA
        ? (Ab + (long)(tid >> 2) * j.lda + m0 + (tid & 3) * 16)
        : (Ab + (long)(m0 + (tid >> 1)) * j.lda + (tid & 1) * 16);
    const uint32_t aSts = TRA ? (uint32_t)((tid >> 2) * 144 + (tid & 3) * 32)
                              : (uint32_t)((tid >> 1) * 80 + (tid & 1) * 32);

    // B staging indices: 32 rows x 4 cols of 16B, both hl per thread
    const int br = tid >> 2, bc = tid & 3;

    const int T = j.Kd / 32;
    float4 fr[4];

    auto loadA = [&](int t) {
        const float* p = TRA ? (aptr + (long)t * 32 * j.lda) : (aptr + t * 32);
        fr[0] = *(const float4*)p;
        fr[1] = *(const float4*)(p + 4);
        fr[2] = *(const float4*)(p + 8);
        fr[3] = *(const float4*)(p + 12);
    };
    auto stsA = [&](int s) {
        uint32_t hp[8], lp[8];
        const float* f = (const float*)fr;
#pragma unroll
        for (int i = 0; i < 8; i++) {
            bf16 h0, l0, h1, l1;
            split_bf(f[2 * i], h0, l0);
            split_bf(f[2 * i + 1], h1, l1);
            hp[i] = (uint32_t)*(uint16_t*)&h0 | ((uint32_t)*(uint16_t*)&h1 << 16);
            lp[i] = (uint32_t)*(uint16_t*)&l0 | ((uint32_t)*(uint16_t*)&l1 << 16);
        }
        char* d0 = smem + (s * 2 + 0) * A_BUF + aSts;
        char* d1 = smem + (s * 2 + 1) * A_BUF + aSts;
        *(uint4*)d0        = make_uint4(hp[0], hp[1], hp[2], hp[3]);
        *(uint4*)(d0 + 16) = make_uint4(hp[4], hp[5], hp[6], hp[7]);
        *(uint4*)d1        = make_uint4(lp[0], lp[1], lp[2], lp[3]);
        *(uint4*)(d1 + 16) = make_uint4(lp[4], lp[5], lp[6], lp[7]);
    };
    auto stageB = [&](int t) {
        const int s = t & 1;
#pragma unroll
        for (int nb = 0; nb < NB; nb++)
#pragma unroll
        for (int hl = 0; hl < 2; hl++) {
            uint32_t dst = sb + BS_OFF + (uint32_t)(((s * NB + nb) * 2 + hl) * B_BUF)
                         + br * 80 + bc * 16;
            cp16(dst, Bb[nb][hl] + (long)br * j.Kd + t * 32 + bc * 8);
        }
        cp_commit();
    };

    // ldmatrix lane addressing
    const uint32_t aLane = TRA
        ? (uint32_t)((((lane & 7) + 8 * (lane >> 4)) * 144) + (w * 16 + ((lane >> 3) & 1) * 8) * 2)
        : (uint32_t)((w * 16 + (lane & 15)) * 80 + (lane >> 4) * 16);
    const uint32_t aKs = TRA ? 2304u : 32u;
    const uint32_t bLaneRow = (uint32_t)((((lane >> 4) & 1) * 8 + (lane & 7)) * 80
                                         + ((lane >> 3) & 1) * 16);

    float acc[NB][4][4];
#pragma unroll
    for (int nb = 0; nb < NB; nb++)
#pragma unroll
        for (int nt = 0; nt < 4; nt++)
#pragma unroll
            for (int r = 0; r < 4; r++) acc[nb][nt][r] = 0.f;

    stageB(0);
    loadA(0);

    for (int t = 0; t < T; t++) {
        const int s = t & 1;
        cp_wait0();
        __syncthreads();

        stsA(s);
        if (t + 1 < T) { stageB(t + 1); loadA(t + 1); }
        __syncthreads();

        const uint32_t aH = sb + (uint32_t)((s * 2 + 0) * A_BUF) + aLane;
        const uint32_t aL = aH + A_BUF;

#pragma unroll
        for (int ks = 0; ks < 2; ks++) {
            uint32_t ah[4], al[4];
            if (TRA) { ldsm4t(ah, aH + ks * aKs); ldsm4t(al, aL + ks * aKs); }
            else     { ldsm4 (ah, aH + ks * aKs); ldsm4 (al, aL + ks * aKs); }
#pragma unroll
            for (int nb = 0; nb < NB; nb++) {
#pragma unroll
                for (int p = 0; p < 2; p++) {
                    uint32_t bbase = sb + BS_OFF + (uint32_t)(((s * NB + nb) * 2 + 0) * B_BUF)
                        + (uint32_t)(p * 16 * 80) + bLaneRow + ks * 32;
                    uint32_t bh[4], bl[4];
                    ldsm4(bh, bbase);
                    ldsm4(bl, bbase + B_BUF);
                    mma_bf(acc[nb][2 * p],     ah, &bh[0]);
                    mma_bf(acc[nb][2 * p],     ah, &bl[0]);
                    mma_bf(acc[nb][2 * p],     al, &bh[0]);
                    mma_bf(acc[nb][2 * p + 1], ah, &bh[2]);
                    mma_bf(acc[nb][2 * p + 1], ah, &bl[2]);
                    mma_bf(acc[nb][2 * p + 1], al, &bh[2]);
                }
            }
        }
    }

    // ---------------- epilogue: stage accs in smem (reuses A region) ---------
    __syncthreads();
    float* Cs = (float*)smem;
    {
        const int g = lane >> 2, cc = lane & 3;
        const int m_l = w * 16 + g;          // 0..63
#pragma unroll
        for (int nb = 0; nb < NB; nb++) {
            float* C_ = Cs + nb * 32 * CST;
#pragma unroll
            for (int nt = 0; nt < 4; nt++) {
                int n0 = nt * 8 + cc * 2;
                C_[(n0 + 0) * CST + m_l]     = acc[nb][nt][0];
                C_[(n0 + 1) * CST + m_l]     = acc[nb][nt][1];
                C_[(n0 + 0) * CST + m_l + 8] = acc[nb][nt][2];
                C_[(n0 + 1) * CST + m_l + 8] = acc[nb][nt][3];
            }
        }
    }
    __syncthreads();

    if (EPI != 3) {
        // write acc0 tile: 32 n x 64 m = 512 float4, 128 threads x 4 iters
#pragma unroll
        for (int it = 0; it < 4; it++) {
            int q = tid + it * 128;
            int n = q >> 4, m4 = (q & 15) * 4;
            float4 v = *(float4*)&Cs[n * CST + m4];
            bf16 h0, l0, h1, l1, h2, l2, h3, l3;
            split_bf(v.x, h0, l0); split_bf(v.y, h1, l1);
            split_bf(v.z, h2, l2); split_bf(v.w, h3, l3);
            long o = ((long)b * 32 + n) * j.Nbig + m0 + m4;
            *(uint2*)(j.Ch + o) = make_uint2(
                ((uint32_t)*(uint16_t*)&h0) | ((uint32_t)*(uint16_t*)&h1 << 16),
                ((uint32_t)*(uint16_t*)&h2) | ((uint32_t)*(uint16_t*)&h3 << 16));
            *(uint2*)(j.Cl + o) = make_uint2(
                ((uint32_t)*(uint16_t*)&l0) | ((uint32_t)*(uint16_t*)&l1 << 16),
                ((uint32_t)*(uint16_t*)&l2) | ((uint32_t)*(uint16_t*)&l3 << 16));
            if (EPI == 1) *(float4*)(j.Cf + o) = v;
        }
    }
    if (EPI == 2) {
        if (tid < 64) {
            float zacc = 0.f;
#pragma unroll
            for (int k = 0; k < KK_; k++)
                zacc += smw[k] * tanhf(Cs[k * CST + tid] + Cs[(32 + k) * CST + tid]);
            j.z[(long)b * j.Nbig + m0 + tid] = zacc;
        }
    }
    if (EPI == 3) {
        if (tid < 64) {
            const float* X = j.Cf + (long)b * 32 * j.Nbig + m0 + tid;
            float zacc = 0.f;
#pragma unroll
            for (int k = 0; k < KK_; k++)
                zacc += smw[k] * tanhf(Cs[k * CST + tid] + X[(long)k * j.Nbig]);
            j.z[(long)b * j.Nbig + m0 + tid] = zacc;
        }
    }
}

// ===================== tail kernels (R10 originals) ============================
__global__ void softmax_kernel(float* __restrict__ z, int n)
{
    const int b = blockIdx.x;
    float* row = z + (long)b * n;
    __shared__ float red[256];
    const int tid = threadIdx.x;

    float mx = -1e30f;
    for (int i = tid; i < n; i += 256) mx = fmaxf(mx, row[i]);
    red[tid] = mx; __syncthreads();
    for (int s = 128; s > 0; s >>= 1) {
        if (tid < s) red[tid] = fmaxf(red[tid], red[tid + s]);
        __syncthreads();
    }
    mx = red[0]; __syncthreads();

    float sum = 0.f;
    for (int i = tid; i < n; i += 256) {
        float e = expf(row[i] - mx);
        row[i] = e;
        sum += e;
    }
    red[tid] = sum; __syncthreads();
    for (int s = 128; s > 0; s >>= 1) {
        if (tid < s) red[tid] += red[tid + s];
        __syncthreads();
    }
    float inv = 1.f / red[0];
    for (int i = tid; i < n; i += 256) row[i] *= inv;
}

__global__ void pool_v_kernel(const float* __restrict__ V,
                              const float* __restrict__ a,
                              float* __restrict__ v1)
{
    const int b = blockIdx.y;
    const int warp = threadIdx.x >> 5;
    const int lane = threadIdx.x & 31;
    const int d = blockIdx.x * 8 + warp;
    const float4* vr = reinterpret_cast<const float4*>(V + ((long)b * D_ + d) * M_);
    const float4* ar = reinterpret_cast<const float4*>(a + (long)b * M_);
    float acc = 0.f;
#pragma unroll
    for (int i = 0; i < M_ / 128; i++) {
        float4 v = vr[i * 32 + lane];
        float4 w = ar[i * 32 + lane];
        acc += v.x * w.x + v.y * w.y + v.z * w.z + v.w * w.w;
    }
#pragma unroll
    for (int o = 16; o > 0; o >>= 1) acc += __shfl_down_sync(0xffffffffu, acc, o);
    if (lane == 0) v1[b * D_ + d] = acc;
}

__global__ void pool_q_kernel(const float* __restrict__ Q,
                              const float* __restrict__ a,
                              float* __restrict__ q1)
{
    const int b = blockIdx.x;
    __shared__ float as[L_];
    for (int i = threadIdx.x; i < L_; i += blockDim.x) as[i] = a[b * L_ + i];
    __syncthreads();
    const int d = threadIdx.x;
    const float* qb = Q + (long)b * L_ * D_;
    float acc = 0.f;
#pragma unroll 8
    for (int l = 0; l < L_; l++) acc += as[l] * qb[(long)l * D_ + d];
    q1[b * D_ + d] = acc;
}

__global__ void bcast_kernel(float4* __restrict__ out,
                             const float4* __restrict__ src,
                             int rows)
{
    const long total4 = (long)B_ * rows * (D_ / 4);
    long i = (long)blockIdx.x * blockDim.x + threadIdx.x;
    if (i >= total4) return;
    int d4 = (int)(i % (D_ / 4));
    long br = i / (D_ / 4);
    int b = (int)(br / rows);
    out[i] = __ldg(&src[(long)b * (D_ / 4) + d4]);
}

// ===================== launch =================================================
extern "C" void kernel_launch(void* const* d_in, const int* in_sizes, int n_in,
                              void* d_out, int out_size)
{
    const float* V   = (const float*)d_in[0];  // [B, D, M]
    const float* Q   = (const float*)d_in[1];  // [B, L, D]
    const float* W_b = (const float*)d_in[2];  // [D, D]
    const float* W_v = (const float*)d_in[3];  // [K, D]
    const float* W_q = (const float*)d_in[4];  // [K, D]
    const float* whv = (const float*)d_in[5];  // [K]
    const float* whq = (const float*)d_in[6];  // [K]
    float* out = (float*)d_out;

    bf16 *pWv_h, *pWv_l, *pWq_h, *pWq_l;
    bf16 *pWqQ_h, *pWqQ_l, *pP_h, *pP_l, *pYv_h, *pYv_l;
    bf16 *pWvV_h, *pWvV_l, *pYq_h, *pYq_l, *pR_h, *pR_l;
    float *pWqQ_f, *pWvV_f, *p_zv, *p_zq, *p_v1, *p_q1;
    cudaGetSymbolAddress((void**)&pWv_h, g_Wv_hi);  cudaGetSymbolAddress((void**)&pWv_l, g_Wv_lo);
    cudaGetSymbolAddress((void**)&pWq_h, g_Wq_hi);  cudaGetSymbolAddress((void**)&pWq_l, g_Wq_lo);
    cudaGetSymbolAddress((void**)&pWqQ_h, g_WqQ_hi); cudaGetSymbolAddress((void**)&pWqQ_l, g_WqQ_lo);
    cudaGetSymbolAddress((void**)&pWqQ_f, g_WqQ_f);
    cudaGetSymbolAddress((void**)&pP_h, g_P_hi);    cudaGetSymbolAddress((void**)&pP_l, g_P_lo);
    cudaGetSymbolAddress((void**)&pYv_h, g_Yv_hi);  cudaGetSymbolAddress((void**)&pYv_l, g_Yv_lo);
    cudaGetSymbolAddress((void**)&pWvV_h, g_WvV_hi); cudaGetSymbolAddress((void**)&pWvV_l, g_WvV_lo);
    cudaGetSymbolAddress((void**)&pWvV_f, g_WvV_f);
    cudaGetSymbolAddress((void**)&pYq_h, g_Yq_hi);  cudaGetSymbolAddress((void**)&pYq_l, g_Yq_lo);
    cudaGetSymbolAddress((void**)&pR_h, g_R_hi);    cudaGetSymbolAddress((void**)&pR_l, g_R_lo);
    cudaGetSymbolAddress((void**)&p_zv, g_zv);      cudaGetSymbolAddress((void**)&p_zq, g_zq);
    cudaGetSymbolAddress((void**)&p_v1, g_v1);      cudaGetSymbolAddress((void**)&p_q1, g_q1);

    const int SM1 = (int)(BS_OFF + 1 * 4 * B_BUF + 128);  // 30848
    cudaFuncSetAttribute(tc_gemm<1, 1, false>, cudaFuncAttributeMaxDynamicSharedMemorySize, SM1);
    cudaFuncSetAttribute(tc_gemm<1, 0, true>,  cudaFuncAttributeMaxDynamicSharedMemorySize, SM1);
    cudaFuncSetAttribute(tc_gemm<1, 1, true>,  cudaFuncAttributeMaxDynamicSharedMemorySize, SM1);
    cudaFuncSetAttribute(tc_gemm<1, 3, true>,  cudaFuncAttributeMaxDynamicSharedMemorySize, SM1);
    cudaFuncSetAttribute(tc_gemm<1, 0, false>, cudaFuncAttributeMaxDynamicSharedMemorySize, SM1);
    cudaFuncSetAttribute(tc_gemm<1, 3, false>, cudaFuncAttributeMaxDynamicSharedMemorySize, SM1);

    // fork/join machinery (host objects only; created+destroyed per call)
    cudaStream_t s2;
    cudaEvent_t evConv, evK1, evK4, evJoin;
    cudaStreamCreateWithFlags(&s2, cudaStreamNonBlocking);
    cudaEventCreateWithFlags(&evConv, cudaEventDisableTiming);
    cudaEventCreateWithFlags(&evK1,   cudaEventDisableTiming);
    cudaEventCreateWithFlags(&evK4,   cudaEventDisableTiming);
    cudaEventCreateWithFlags(&evJoin, cudaEventDisableTiming);

    conv_pad<<<(32 * D_ + 255) / 256, 256>>>(W_v, pWv_h, pWv_l, W_q, pWq_h, pWq_l);
    cudaEventRecord(evConv, 0);
    cudaStreamWaitEvent(s2, evConv, 0);

    GJob j;

    // ================= stream 2 chain: K4 -> K6 -> K7 -> K8 -> q-tail ========
    // K4: WvV[k,m] = sum_d Wv[k,d] V[d,m] : A=V TRA (lda=M); hi/lo + fp32 out
    j = { V, M_, (long)D_ * M_, pWv_h, pWv_l, nullptr, nullptr,
          pWvV_h, pWvV_l, pWvV_f, nullptr, nullptr, M_, D_, 0, 0 };
    tc_gemm<1, 1, true><<<dim3(M_ / 64, B_), 128, SM1, s2>>>(j);
    cudaEventRecord(evK4, s2);

    // K6: Yq[k,e] = sum_m WvV[k,m] V[e,m] : A=V AN [D][M], Kd=M
    j = { V, M_, (long)D_ * M_, pWvV_h, pWvV_l, nullptr, nullptr,
          pYq_h, pYq_l, nullptr, nullptr, nullptr, D_, M_, (long)32 * M_, 0 };
    tc_gemm<1, 0, false><<<dim3(D_ / 64, B_), 128, SM1, s2>>>(j);

    // K7: R[k,d] = sum_e Yq[k,e] Wb[d,e] : A=Wb AN (no batch)
    j = { W_b, D_, 0, pYq_h, pYq_l, nullptr, nullptr,
          pR_h, pR_l, nullptr, nullptr, nullptr, D_, D_, (long)32 * D_, 0 };
    tc_gemm<1, 0, false><<<dim3(D_ / 64, B_), 128, SM1, s2>>>(j);

    // ================= stream 0 chain: K1 -> K2 -> K3 -> K5' -> v-tail =======
    // K1: WqQ[k,l] = sum_d Wq[k,d] Q[l,d] : A=Q AN [L][D]; hi/lo + fp32 out
    j = { Q, D_, (long)L_ * D_, pWq_h, pWq_l, nullptr, nullptr,
          pWqQ_h, pWqQ_l, pWqQ_f, nullptr, nullptr, L_, D_, 0, 0 };
    tc_gemm<1, 1, false><<<dim3(L_ / 64, B_), 128, SM1>>>(j);
    cudaEventRecord(evK1, 0);

    // K2: P[k,e] = sum_l WqQ[k,l] Q[l,e] : A=Q TRA (lda=D), Kd=L
    j = { Q, D_, (long)L_ * D_, pWqQ_h, pWqQ_l, nullptr, nullptr,
          pP_h, pP_l, nullptr, nullptr, nullptr, D_, L_, (long)32 * L_, 0 };
    tc_gemm<1, 0, true><<<dim3(D_ / 64, B_), 128, SM1>>>(j);

    // K3: Yv[k,e] = sum_d P[k,d] Wb[d,e] : A=Wb TRA (no batch)
    j = { W_b, D_, 0, pP_h, pP_l, nullptr, nullptr,
          pYv_h, pYv_l, nullptr, nullptr, nullptr, D_, D_, (long)32 * D_, 0 };
    tc_gemm<1, 0, true><<<dim3(D_ / 64, B_), 128, SM1>>>(j);

    // K5': z_v = sum_k w tanh(WvV_f + Yv x V) : A=V TRA; B=Yv; X=WvV_f
    cudaStreamWaitEvent(0, evK4, 0);
    j = { V, M_, (long)D_ * M_, pYv_h, pYv_l, nullptr, nullptr,
          nullptr, nullptr, pWvV_f, whv, p_zv, M_, D_, (long)32 * D_, 0 };
    tc_gemm<1, 3, true><<<dim3(M_ / 64, B_), 128, SM1>>>(j);

    // v-tail on stream 0
    softmax_kernel<<<B_, 256>>>(p_zv, M_);
    {
        dim3 grid(D_ / 8, B_);
        pool_v_kernel<<<grid, 256>>>(V, p_zv, p_v1);
    }
    {
        long n4v = (long)B_ * M_ * (D_ / 4);
        bcast_kernel<<<(unsigned)((n4v + 255) / 256), 256>>>(
            (float4*)out, (const float4*)p_v1, M_);
    }

    // ================= stream 2 continues: K8 + q-tail ========================
    cudaStreamWaitEvent(s2, evK1, 0);   // K8 needs WqQ_f (done long ago)
    j = { Q, D_, (long)L_ * D_, pR_h, pR_l, nullptr, nullptr,
          nullptr, nullptr, pWqQ_f, whq, p_zq, L_, D_, (long)32 * D_, 0 };
    tc_gemm<1, 3, false><<<dim3(L_ / 64, B_), 128, SM1, s2>>>(j);

    softmax_kernel<<<B_, 256, 0, s2>>>(p_zq, L_);
    pool_q_kernel<<<B_, 512, 0, s2>>>(Q, p_zq, p_q1);
    {
        long n4q = (long)B_ * L_ * (D_ / 4);
        float* out_q = out + (long)B_ * M_ * D_;
        bcast_kernel<<<(unsigned)((n4q + 255) / 256), 256, 0, s2>>>(
            (float4*)out_q, (const float4*)p_q1, L_);
    }

    // ---- join: default stream waits for stream-2 chain
    cudaEventRecord(evJoin, s2);
    cudaStreamWaitEvent(0, evJoin, 0);

    cudaEventDestroy(evConv);
    cudaEventDestroy(evK1);
    cudaEventDestroy(evK4);
    cudaEventDestroy(evJoin);
    cudaStreamDestroy(s2);
}